// round 10
// baseline (speedup 1.0000x reference)
#include <cuda_runtime.h>
#include <cuda_bf16.h>
#include <cstdint>

#define THREADS 512
#define TILE_M  128
#define D_DIM   128
#define K_RBF   64

// strides in bf16 elements
#define W_STR   136      // 128 + 8 pad
#define A1_STR  72       // 64 + 8 pad
#define A2_STR  136
#define FB_STR  130      // floats per fbuf row

// ---------------- smem layout (bytes) ----------------
#define OFF_W1HI 0
#define OFF_W1LO (OFF_W1HI + K_RBF * W_STR * 2)       // 17408
#define OFF_W2HI (OFF_W1LO + K_RBF * W_STR * 2)       // 34816
#define OFF_W2LO (OFF_W2HI + D_DIM * W_STR * 2)       // 69632
#define OFF_A1HI (OFF_W2LO + D_DIM * W_STR * 2)       // 104448
#define OFF_A1LO (OFF_A1HI + TILE_M * A1_STR * 2)     // 122880
#define OFF_A2HI (OFF_A1LO + TILE_M * A1_STR * 2)     // 141312
#define OFF_A2LO (OFF_A2HI + TILE_M * A2_STR * 2)     // 176128
#define OFF_FBUF OFF_A2HI                              // overlay A2 (guarded)
#define OFF_B1S  (OFF_A2LO + TILE_M * A2_STR * 2)     // 210944
#define OFF_B2S  (OFF_B1S + 512)
#define OFF_CEN  (OFF_B2S + 512)
#define OFF_GAM  (OFF_CEN + 256)
#define OFF_EMS  (OFF_GAM + 256)                       // int2[2][128]
#define SMEM_TOTAL (OFF_EMS + 2048)                    // 214528

// ---------------- PTX helpers ----------------
static __device__ __forceinline__ uint32_t smem_u32(const void* p) {
    uint32_t a;
    asm("{ .reg .u64 t; cvta.to.shared.u64 t, %1; cvt.u32.u64 %0, t; }" : "=r"(a) : "l"(p));
    return a;
}

#define BAR_GRP(id) asm volatile("bar.sync %0, %1;" :: "r"(id), "r"(128) : "memory")

#define LDSM_X4(r, addr)                                                     \
    asm volatile("ldmatrix.sync.aligned.m8n8.x4.shared.b16 {%0,%1,%2,%3}, [%4];" \
        : "=r"((r)[0]), "=r"((r)[1]), "=r"((r)[2]), "=r"((r)[3]) : "r"(addr))

#define LDSM_X4T(r, addr)                                                    \
    asm volatile("ldmatrix.sync.aligned.m8n8.x4.trans.shared.b16 {%0,%1,%2,%3}, [%4];" \
        : "=r"((r)[0]), "=r"((r)[1]), "=r"((r)[2]), "=r"((r)[3]) : "r"(addr))

// NOTE: non-volatile — mma.sync touches registers only; constraints carry all
// dataflow. Lets ptxas software-pipeline MMAs against LDSM and each other.
#define MMA_BF16(c, a, b0, b1)                                               \
    asm("mma.sync.aligned.m16n8k16.row.col.f32.bf16.bf16.f32 "              \
        "{%0,%1,%2,%3}, {%4,%5,%6,%7}, {%8,%9}, {%0,%1,%2,%3};"             \
        : "+f"((c)[0]), "+f"((c)[1]), "+f"((c)[2]), "+f"((c)[3])            \
        : "r"((a)[0]), "r"((a)[1]), "r"((a)[2]), "r"((a)[3]),               \
          "r"(b0), "r"(b1))

static __device__ __forceinline__ float ssp(float x) {
    return fmaxf(x, 0.f) + __logf(1.f + __expf(-fabsf(x))) - 0.69314718055994531f;
}

// packed split: (f0,f1) -> hi bf16x2 (f1 in upper), lo bf16x2 residual
static __device__ __forceinline__ void split_pair(float f0, float f1,
                                                  uint32_t& hp, uint32_t& lp) {
    asm("cvt.rn.bf16x2.f32 %0, %1, %2;" : "=r"(hp) : "f"(f1), "f"(f0));
    const float h0 = __uint_as_float(hp << 16);
    const float h1 = __uint_as_float(hp & 0xFFFF0000u);
    asm("cvt.rn.bf16x2.f32 %0, %1, %2;" : "=r"(lp) : "f"(f1 - h1), "f"(f0 - h0));
}

static __device__ __forceinline__ void bf16_split(float f, uint16_t& hi, uint16_t& lo) {
    __nv_bfloat16 h = __float2bfloat16(f);
    float r = f - __bfloat162float(h);
    __nv_bfloat16 l = __float2bfloat16(r);
    hi = *reinterpret_cast<uint16_t*>(&h);
    lo = *reinterpret_cast<uint16_t*>(&l);
}

__global__ void zero_out_kernel(float* __restrict__ out, size_t n) {
    size_t i = (size_t)blockIdx.x * blockDim.x + threadIdx.x;
    size_t stride = (size_t)gridDim.x * blockDim.x;
    for (; i < n; i += stride) out[i] = 0.f;
}

extern __shared__ char smem[];

__global__ void __launch_bounds__(THREADS, 1)
cfconv_mma_kernel(const float* __restrict__ AF,     // [B,N,D]
                  const float* __restrict__ dist,   // [B,E]
                  const int*   __restrict__ idx_j,  // [E]
                  const int*   __restrict__ seg_i,  // [E] sorted
                  const float* __restrict__ W1,     // [K,D]
                  const float* __restrict__ b1,
                  const float* __restrict__ W2,     // [D,D]
                  const float* __restrict__ b2,
                  const float* __restrict__ centers,
                  const float* __restrict__ gamma,
                  float* __restrict__ out,          // [B,N,D]
                  int B, int N, int E)
{
    const uint32_t sb = smem_u32(smem);
    const int tid  = threadIdx.x;
    const int w    = tid >> 5;
    const int lane = tid & 31;

    float* b1s = (float*)(smem + OFF_B1S);
    float* b2s = (float*)(smem + OFF_B2S);
    float* cen = (float*)(smem + OFF_CEN);
    float* gam = (float*)(smem + OFF_GAM);
    float* fb  = (float*)(smem + OFF_FBUF);

    // ---- weight prep: bf16 hi/lo, padded row-major [K][D] ----
    for (int i = tid; i < K_RBF * D_DIM; i += THREADS) {
        const int k = i >> 7, d = i & 127;
        uint16_t hi, lo; bf16_split(W1[i], hi, lo);
        *(uint16_t*)(smem + OFF_W1HI + (k * W_STR + d) * 2) = hi;
        *(uint16_t*)(smem + OFF_W1LO + (k * W_STR + d) * 2) = lo;
    }
    for (int i = tid; i < D_DIM * D_DIM; i += THREADS) {
        const int k = i >> 7, d = i & 127;
        uint16_t hi, lo; bf16_split(W2[i], hi, lo);
        *(uint16_t*)(smem + OFF_W2HI + (k * W_STR + d) * 2) = hi;
        *(uint16_t*)(smem + OFF_W2LO + (k * W_STR + d) * 2) = lo;
    }
    if (tid < D_DIM) { b1s[tid] = b1[tid]; b2s[tid] = b2[tid]; }
    if (tid >= 128 && tid < 128 + K_RBF) {
        const int k = tid - 128; cen[k] = centers[k]; gam[k] = gamma[k];
    }
    __syncthreads();

    // warp tiling: 4x4 warp grid, each warp owns 32 edges x 32 cols
    const int wm = w & 3;              // row group (barrier id 1+wm)
    const int wn = w >> 2;             // col group
    const int r0 = wm * 32;
    const int d0 = wn * 32;
    const int arow = lane & 15;
    const int acol = (lane >> 4) * 8;
    const int gr   = lane >> 2;
    const int cc   = (lane & 3) * 2;

    const int tiles_pb = (E + TILE_M - 1) / TILE_M;
    const int total    = B * tiles_pb;

    // RBF phase for a tile: writes A1 + meta (ems[par])
    auto rbf_phase = [&](int gidx, int par) {
        const int bb_ = gidx / tiles_pb;
        const int e0_ = (gidx - bb_ * tiles_pb) * TILE_M;
        const int ne_ = min(TILE_M, E - e0_);
        const float* db_ = dist + (size_t)bb_ * E;
        const int el = r0 + lane;             // own group's edge row
        const int kb = wn * 16;
        const int eg = e0_ + min(el, ne_ - 1);
        const float dv = __ldg(&db_[eg]);
        #pragma unroll
        for (int kk = 0; kk < 16; kk += 2) {
            const int k = kb + kk;
            const float t0 = dv - cen[k];
            const float t1 = dv - cen[k + 1];
            const float v0 = __expf(-gam[k]     * t0 * t0);
            const float v1 = __expf(-gam[k + 1] * t1 * t1);
            uint32_t hp, lp;
            split_pair(v0, v1, hp, lp);
            const uint32_t byt = (uint32_t)(el * A1_STR + k) * 2;
            *(uint32_t*)(smem + OFF_A1HI + byt) = hp;
            *(uint32_t*)(smem + OFF_A1LO + byt) = lp;
        }
        if (tid < TILE_M) {
            const int e = e0_ + min(tid, ne_ - 1);
            ((int2*)(smem + OFF_EMS))[par * 128 + tid] =
                make_int2(__ldg(&idx_j[e]), __ldg(&seg_i[e]));
        }
    };

    int parity = 0;
    const int g0 = blockIdx.x;
    if (g0 < total) rbf_phase(g0, parity);
    __syncthreads();

    for (int g = g0; g < total; g += gridDim.x) {
        const int b  = g / tiles_pb;
        const int e0 = (g - b * tiles_pb) * TILE_M;
        const int ne = min(TILE_M, E - e0);

        float c[2][4][4];
        #pragma unroll
        for (int mt = 0; mt < 2; mt++)
            #pragma unroll
            for (int nt = 0; nt < 4; nt++)
                { c[mt][nt][0]=0.f; c[mt][nt][1]=0.f; c[mt][nt][2]=0.f; c[mt][nt][3]=0.f; }

        // -------- GEMM1: [32x64] x W1[:,d0:d0+32] --------
        #pragma unroll
        for (int k = 0; k < 4; k++) {
            uint32_t ah[2][4], al[2][4];
            #pragma unroll
            for (int mt = 0; mt < 2; mt++) {
                const uint32_t ab = (uint32_t)((r0 + mt*16 + arow) * A1_STR + k*16 + acol) * 2;
                LDSM_X4(ah[mt], sb + OFF_A1HI + ab);
                LDSM_X4(al[mt], sb + OFF_A1LO + ab);
            }
            const uint32_t brow = (uint32_t)((k*16 + arow) * W_STR + d0 + acol) * 2;
            #pragma unroll
            for (int p = 0; p < 2; p++) {
                uint32_t bh[4], bl[4];
                const uint32_t bbad = brow + (uint32_t)(p * 16) * 2;
                LDSM_X4T(bh, sb + OFF_W1HI + bbad);
                LDSM_X4T(bl, sb + OFF_W1LO + bbad);
                // hi terms for all 4 accumulators, then al, then bl:
                // each accumulator revisited only after 3 other MMAs.
                #pragma unroll
                for (int q = 0; q < 2; q++)
                    #pragma unroll
                    for (int mt = 0; mt < 2; mt++)
                        MMA_BF16(c[mt][2*p+q], ah[mt], bh[2*q], bh[2*q+1]);
                #pragma unroll
                for (int q = 0; q < 2; q++)
                    #pragma unroll
                    for (int mt = 0; mt < 2; mt++)
                        MMA_BF16(c[mt][2*p+q], al[mt], bh[2*q], bh[2*q+1]);
                #pragma unroll
                for (int q = 0; q < 2; q++)
                    #pragma unroll
                    for (int mt = 0; mt < 2; mt++)
                        MMA_BF16(c[mt][2*p+q], ah[mt], bl[2*q], bl[2*q+1]);
            }
        }

        // -------- Epilogue 1: +b1, ssp, split -> A2 (own rows/cols) --------
        #pragma unroll
        for (int mt = 0; mt < 2; mt++) {
            #pragma unroll
            for (int nt = 0; nt < 4; nt++) {
                const int col = d0 + nt*8 + cc;
                const float f0 = ssp(c[mt][nt][0] + b1s[col]);
                const float f1 = ssp(c[mt][nt][1] + b1s[col + 1]);
                const float f2 = ssp(c[mt][nt][2] + b1s[col]);
                const float f3 = ssp(c[mt][nt][3] + b1s[col + 1]);
                uint32_t hp0, lp0, hp1, lp1;
                split_pair(f0, f1, hp0, lp0);
                split_pair(f2, f3, hp1, lp1);
                const uint32_t r0b = (uint32_t)((r0 + mt*16 + gr)     * A2_STR + col) * 2;
                const uint32_t r1b = (uint32_t)((r0 + mt*16 + gr + 8) * A2_STR + col) * 2;
                *(uint32_t*)(smem + OFF_A2HI + r0b) = hp0;
                *(uint32_t*)(smem + OFF_A2LO + r0b) = lp0;
                *(uint32_t*)(smem + OFF_A2HI + r1b) = hp1;
                *(uint32_t*)(smem + OFF_A2LO + r1b) = lp1;
                c[mt][nt][0]=0.f; c[mt][nt][1]=0.f; c[mt][nt][2]=0.f; c[mt][nt][3]=0.f;
            }
        }
        BAR_GRP(1 + wm);   // A2 rows of this group complete

        // -------- GEMM2: [32x128] x W2[:,d0:d0+32] --------
        #pragma unroll
        for (int k = 0; k < 8; k++) {
            uint32_t ah[2][4], al[2][4];
            #pragma unroll
            for (int mt = 0; mt < 2; mt++) {
                const uint32_t ab = (uint32_t)((r0 + mt*16 + arow) * A2_STR + k*16 + acol) * 2;
                LDSM_X4(ah[mt], sb + OFF_A2HI + ab);
                LDSM_X4(al[mt], sb + OFF_A2LO + ab);
            }
            const uint32_t brow = (uint32_t)((k*16 + arow) * W_STR + d0 + acol) * 2;
            #pragma unroll
            for (int p = 0; p < 2; p++) {
                uint32_t bh[4], bl[4];
                const uint32_t bbad = brow + (uint32_t)(p * 16) * 2;
                LDSM_X4T(bh, sb + OFF_W2HI + bbad);
                LDSM_X4T(bl, sb + OFF_W2LO + bbad);
                #pragma unroll
                for (int q = 0; q < 2; q++)
                    #pragma unroll
                    for (int mt = 0; mt < 2; mt++)
                        MMA_BF16(c[mt][2*p+q], ah[mt], bh[2*q], bh[2*q+1]);
                #pragma unroll
                for (int q = 0; q < 2; q++)
                    #pragma unroll
                    for (int mt = 0; mt < 2; mt++)
                        MMA_BF16(c[mt][2*p+q], al[mt], bh[2*q], bh[2*q+1]);
                #pragma unroll
                for (int q = 0; q < 2; q++)
                    #pragma unroll
                    for (int mt = 0; mt < 2; mt++)
                        MMA_BF16(c[mt][2*p+q], ah[mt], bl[2*q], bl[2*q+1]);
            }
        }
        __syncthreads();   // ALL A2 reads done before fbuf (A2 overlay) writes

        // -------- Epilogue 2: +b2, ssp -> fbuf (fp32, overlays A2) --------
        #pragma unroll
        for (int mt = 0; mt < 2; mt++) {
            #pragma unroll
            for (int nt = 0; nt < 4; nt++) {
                const int col = d0 + nt*8 + cc;
                const float f0 = ssp(c[mt][nt][0] + b2s[col]);
                const float f1 = ssp(c[mt][nt][1] + b2s[col + 1]);
                const float f2 = ssp(c[mt][nt][2] + b2s[col]);
                const float f3 = ssp(c[mt][nt][3] + b2s[col + 1]);
                *(float2*)&fb[(r0 + mt*16 + gr)     * FB_STR + col] = make_float2(f0, f1);
                *(float2*)&fb[(r0 + mt*16 + gr + 8) * FB_STR + col] = make_float2(f2, f3);
            }
        }
        __syncthreads();

        // -------- Overlap: RBF(next tile) -> A1  ||  gather(g) from fbuf --------
        const int gnext = g + gridDim.x;
        if (gnext < total) rbf_phase(gnext, parity ^ 1);

        {
            const int2* ems = (const int2*)(smem + OFF_EMS) + parity * 128;
            const int ch = (tid & 63) * 2;      // channel pair
            const int sp = tid >> 6;            // span 0..7 (16 edges each)
            const float* AFp = AF + (size_t)b * N * D_DIM;
            float*       Op  = out + (size_t)b * N * D_DIM;
            int cur = -1; float2 acc = make_float2(0.f, 0.f);
            const int e_beg = sp * 16;

            if (ne == TILE_M) {
                #pragma unroll
                for (int chk = 0; chk < 2; chk++) {
                    const int eb = e_beg + chk * 8;
                    float2 m[8]; int sr[8];
                    #pragma unroll
                    for (int e = 0; e < 8; e++) {
                        const int2 js = ems[eb + e];
                        sr[e] = js.y;
                        const float2 af = *(const float2*)&AFp[(size_t)js.x * D_DIM + ch];
                        const float2 f  = *(const float2*)&fb[(eb + e) * FB_STR + ch];
                        m[e] = make_float2(af.x * f.x, af.y * f.y);
                    }
                    #pragma unroll
                    for (int e = 0; e < 8; e++) {
                        if (sr[e] != cur) {
                            if (cur >= 0) {
                                atomicAdd(&Op[(size_t)cur * D_DIM + ch],     acc.x);
                                atomicAdd(&Op[(size_t)cur * D_DIM + ch + 1], acc.y);
                            }
                            cur = sr[e]; acc = m[e];
                        } else { acc.x += m[e].x; acc.y += m[e].y; }
                    }
                }
            } else {
                const int e_end = min(e_beg + 16, ne);
                for (int e = e_beg; e < e_end; e++) {
                    const int2 js = ems[e];
                    const float2 af = *(const float2*)&AFp[(size_t)js.x * D_DIM + ch];
                    const float2 f  = *(const float2*)&fb[e * FB_STR + ch];
                    const float2 m  = make_float2(af.x * f.x, af.y * f.y);
                    if (js.y != cur) {
                        if (cur >= 0) {
                            atomicAdd(&Op[(size_t)cur * D_DIM + ch],     acc.x);
                            atomicAdd(&Op[(size_t)cur * D_DIM + ch + 1], acc.y);
                        }
                        cur = js.y; acc = m;
                    } else { acc.x += m.x; acc.y += m.y; }
                }
            }
            if (cur >= 0) {
                atomicAdd(&Op[(size_t)cur * D_DIM + ch],     acc.x);
                atomicAdd(&Op[(size_t)cur * D_DIM + ch + 1], acc.y);
            }
        }
        parity ^= 1;
        __syncthreads();   // gather done (fbuf free) & A1 ready for next GEMM1
    }
}

extern "C" void kernel_launch(void* const* d_in, const int* in_sizes, int n_in,
                              void* d_out, int out_size) {
    // order: atom_features, distances, idx_j, seg_i, centers, gamma, W1, b1, W2, b2
    const float* AF      = (const float*)d_in[0];
    const float* dist    = (const float*)d_in[1];
    const int*   idx_j   = (const int*)  d_in[2];
    const int*   seg_i   = (const int*)  d_in[3];
    const float* centers = (const float*)d_in[4];
    const float* gamma   = (const float*)d_in[5];
    const float* W1      = (const float*)d_in[6];
    const float* b1      = (const float*)d_in[7];
    const float* W2      = (const float*)d_in[8];
    const float* b2      = (const float*)d_in[9];
    float* out = (float*)d_out;

    const int E = in_sizes[2];
    const int B = in_sizes[1] / E;
    const int D = in_sizes[7];              // 128
    const int N = in_sizes[0] / (B * D);

    zero_out_kernel<<<2048, 256>>>(out, (size_t)out_size);

    cudaFuncSetAttribute(cfconv_mma_kernel,
                         cudaFuncAttributeMaxDynamicSharedMemorySize, SMEM_TOTAL);
    cfconv_mma_kernel<<<148, THREADS, SMEM_TOTAL>>>(
        AF, dist, idx_j, seg_i, W1, b1, W2, b2, centers, gamma, out, B, N, E);
}

// round 11
// speedup vs baseline: 1.1849x; 1.1849x over previous
#include <cuda_runtime.h>
#include <cuda_fp16.h>
#include <cstdint>

#define THREADS 512
#define TILE_M  128
#define D_DIM   128
#define K_RBF   64

// strides in fp16 elements
#define W_STR   136      // 128 + 8 pad
#define A1_STR  72       // 64 + 8 pad
#define A2_STR  136
#define FB_STR  130      // floats per fbuf row

// ---------------- smem layout (bytes) ----------------
#define OFF_W1H  0
#define OFF_W2H  (OFF_W1H + K_RBF * W_STR * 2)        // 17408
#define OFF_A1HI (OFF_W2H + D_DIM * W_STR * 2)        // 52224
#define OFF_A1LO (OFF_A1HI + TILE_M * A1_STR * 2)     // 70656
#define OFF_A2HI (OFF_A1LO + TILE_M * A1_STR * 2)     // 89088
#define OFF_A2LO (OFF_A2HI + TILE_M * A2_STR * 2)     // 123904
#define OFF_FBUF OFF_A2HI                              // overlay A2 (66560 <= 69632)
#define OFF_B1S  (OFF_A2LO + TILE_M * A2_STR * 2)     // 158720
#define OFF_B2S  (OFF_B1S + 512)
#define OFF_CEN  (OFF_B2S + 512)
#define OFF_GAM  (OFF_CEN + 256)
#define OFF_EMS  (OFF_GAM + 256)                       // int2[2][128]
#define SMEM_TOTAL (OFF_EMS + 2048)                    // 162304

// ---------------- PTX helpers ----------------
static __device__ __forceinline__ uint32_t smem_u32(const void* p) {
    uint32_t a;
    asm("{ .reg .u64 t; cvta.to.shared.u64 t, %1; cvt.u32.u64 %0, t; }" : "=r"(a) : "l"(p));
    return a;
}

#define BAR_GRP(id) asm volatile("bar.sync %0, %1;" :: "r"(id), "r"(128) : "memory")

#define LDSM_X4(r, addr)                                                     \
    asm volatile("ldmatrix.sync.aligned.m8n8.x4.shared.b16 {%0,%1,%2,%3}, [%4];" \
        : "=r"((r)[0]), "=r"((r)[1]), "=r"((r)[2]), "=r"((r)[3]) : "r"(addr))

#define LDSM_X4T(r, addr)                                                    \
    asm volatile("ldmatrix.sync.aligned.m8n8.x4.trans.shared.b16 {%0,%1,%2,%3}, [%4];" \
        : "=r"((r)[0]), "=r"((r)[1]), "=r"((r)[2]), "=r"((r)[3]) : "r"(addr))

#define MMA_F16(c, a, b0, b1)                                                \
    asm("mma.sync.aligned.m16n8k16.row.col.f32.f16.f16.f32 "                \
        "{%0,%1,%2,%3}, {%4,%5,%6,%7}, {%8,%9}, {%0,%1,%2,%3};"             \
        : "+f"((c)[0]), "+f"((c)[1]), "+f"((c)[2]), "+f"((c)[3])            \
        : "r"((a)[0]), "r"((a)[1]), "r"((a)[2]), "r"((a)[3]),               \
          "r"(b0), "r"(b1))

static __device__ __forceinline__ float ssp(float x) {
    return fmaxf(x, 0.f) + __logf(1.f + __expf(-fabsf(x))) - 0.69314718055994531f;
}

// packed fp16 split: (f0,f1) -> hi f16x2 (f1 upper), lo f16x2 residual
static __device__ __forceinline__ void split_pair(float f0, float f1,
                                                  uint32_t& hp, uint32_t& lp) {
    asm("cvt.rn.f16x2.f32 %0, %1, %2;" : "=r"(hp) : "f"(f1), "f"(f0));
    const __half2 h2 = *reinterpret_cast<const __half2*>(&hp);
    const float h0 = __low2float(h2);
    const float h1 = __high2float(h2);
    asm("cvt.rn.f16x2.f32 %0, %1, %2;" : "=r"(lp) : "f"(f1 - h1), "f"(f0 - h0));
}

__global__ void zero_out_kernel(float* __restrict__ out, size_t n) {
    size_t i = (size_t)blockIdx.x * blockDim.x + threadIdx.x;
    size_t stride = (size_t)gridDim.x * blockDim.x;
    for (; i < n; i += stride) out[i] = 0.f;
}

extern __shared__ char smem[];

__global__ void __launch_bounds__(THREADS, 1)
cfconv_mma_kernel(const float* __restrict__ AF,     // [B,N,D]
                  const float* __restrict__ dist,   // [B,E]
                  const int*   __restrict__ idx_j,  // [E]
                  const int*   __restrict__ seg_i,  // [E] sorted
                  const float* __restrict__ W1,     // [K,D]
                  const float* __restrict__ b1,
                  const float* __restrict__ W2,     // [D,D]
                  const float* __restrict__ b2,
                  const float* __restrict__ centers,
                  const float* __restrict__ gamma,
                  float* __restrict__ out,          // [B,N,D]
                  int B, int N, int E)
{
    const uint32_t sb = smem_u32(smem);
    const int tid  = threadIdx.x;
    const int w    = tid >> 5;
    const int lane = tid & 31;

    float* b1s = (float*)(smem + OFF_B1S);
    float* b2s = (float*)(smem + OFF_B2S);
    float* cen = (float*)(smem + OFF_CEN);
    float* gam = (float*)(smem + OFF_GAM);
    float* fb  = (float*)(smem + OFF_FBUF);

    // ---- weight prep: fp16 (hi only), padded row-major [K][D] ----
    for (int i = tid; i < K_RBF * D_DIM; i += THREADS) {
        const int k = i >> 7, d = i & 127;
        *(__half*)(smem + OFF_W1H + (k * W_STR + d) * 2) = __float2half_rn(W1[i]);
    }
    for (int i = tid; i < D_DIM * D_DIM; i += THREADS) {
        const int k = i >> 7, d = i & 127;
        *(__half*)(smem + OFF_W2H + (k * W_STR + d) * 2) = __float2half_rn(W2[i]);
    }
    if (tid < D_DIM) { b1s[tid] = b1[tid]; b2s[tid] = b2[tid]; }
    if (tid >= 128 && tid < 128 + K_RBF) {
        const int k = tid - 128; cen[k] = centers[k]; gam[k] = gamma[k];
    }
    __syncthreads();

    // warp tiling: 4x4 warp grid, each warp owns 32 edges x 32 cols
    const int wm = w & 3;              // row group (barrier id 1+wm)
    const int wn = w >> 2;             // col group
    const int r0 = wm * 32;
    const int d0 = wn * 32;
    const int arow = lane & 15;
    const int acol = (lane >> 4) * 8;
    const int gr   = lane >> 2;
    const int cc   = (lane & 3) * 2;

    const int tiles_pb = (E + TILE_M - 1) / TILE_M;
    const int total    = B * tiles_pb;

    // RBF phase for a tile: writes A1 + meta (ems[par])
    auto rbf_phase = [&](int gidx, int par) {
        const int bb_ = gidx / tiles_pb;
        const int e0_ = (gidx - bb_ * tiles_pb) * TILE_M;
        const int ne_ = min(TILE_M, E - e0_);
        const float* db_ = dist + (size_t)bb_ * E;
        const int el = r0 + lane;             // own group's edge row
        const int kb = wn * 16;
        const int eg = e0_ + min(el, ne_ - 1);
        const float dv = __ldg(&db_[eg]);
        #pragma unroll
        for (int kk = 0; kk < 16; kk += 2) {
            const int k = kb + kk;
            const float t0 = dv - cen[k];
            const float t1 = dv - cen[k + 1];
            const float v0 = __expf(-gam[k]     * t0 * t0);
            const float v1 = __expf(-gam[k + 1] * t1 * t1);
            uint32_t hp, lp;
            split_pair(v0, v1, hp, lp);
            const uint32_t byt = (uint32_t)(el * A1_STR + k) * 2;
            *(uint32_t*)(smem + OFF_A1HI + byt) = hp;
            *(uint32_t*)(smem + OFF_A1LO + byt) = lp;
        }
        if (tid < TILE_M) {
            const int e = e0_ + min(tid, ne_ - 1);
            ((int2*)(smem + OFF_EMS))[par * 128 + tid] =
                make_int2(__ldg(&idx_j[e]), __ldg(&seg_i[e]));
        }
    };

    int parity = 0;
    const int g0 = blockIdx.x;
    if (g0 < total) rbf_phase(g0, parity);
    __syncthreads();

    for (int g = g0; g < total; g += gridDim.x) {
        const int b  = g / tiles_pb;
        const int e0 = (g - b * tiles_pb) * TILE_M;
        const int ne = min(TILE_M, E - e0);

        float c[2][4][4];
        #pragma unroll
        for (int mt = 0; mt < 2; mt++)
            #pragma unroll
            for (int nt = 0; nt < 4; nt++)
                { c[mt][nt][0]=0.f; c[mt][nt][1]=0.f; c[mt][nt][2]=0.f; c[mt][nt][3]=0.f; }

        // -------- GEMM1: [32x64] x W1[:,d0:d0+32]  (a_hi + a_lo) x b_hi --------
        #pragma unroll
        for (int k = 0; k < 4; k++) {
            uint32_t ah[2][4], al[2][4];
            #pragma unroll
            for (int mt = 0; mt < 2; mt++) {
                const uint32_t ab = (uint32_t)((r0 + mt*16 + arow) * A1_STR + k*16 + acol) * 2;
                LDSM_X4(ah[mt], sb + OFF_A1HI + ab);
                LDSM_X4(al[mt], sb + OFF_A1LO + ab);
            }
            const uint32_t brow = (uint32_t)((k*16 + arow) * W_STR + d0 + acol) * 2;
            #pragma unroll
            for (int p = 0; p < 2; p++) {
                uint32_t bh[4];
                LDSM_X4T(bh, sb + OFF_W1H + brow + (uint32_t)(p * 16) * 2);
                #pragma unroll
                for (int q = 0; q < 2; q++)
                    #pragma unroll
                    for (int mt = 0; mt < 2; mt++)
                        MMA_F16(c[mt][2*p+q], ah[mt], bh[2*q], bh[2*q+1]);
                #pragma unroll
                for (int q = 0; q < 2; q++)
                    #pragma unroll
                    for (int mt = 0; mt < 2; mt++)
                        MMA_F16(c[mt][2*p+q], al[mt], bh[2*q], bh[2*q+1]);
            }
        }

        // -------- Epilogue 1: +b1, ssp, fp16 split -> A2 --------
        #pragma unroll
        for (int mt = 0; mt < 2; mt++) {
            #pragma unroll
            for (int nt = 0; nt < 4; nt++) {
                const int col = d0 + nt*8 + cc;
                const float f0 = ssp(c[mt][nt][0] + b1s[col]);
                const float f1 = ssp(c[mt][nt][1] + b1s[col + 1]);
                const float f2 = ssp(c[mt][nt][2] + b1s[col]);
                const float f3 = ssp(c[mt][nt][3] + b1s[col + 1]);
                uint32_t hp0, lp0, hp1, lp1;
                split_pair(f0, f1, hp0, lp0);
                split_pair(f2, f3, hp1, lp1);
                const uint32_t r0b = (uint32_t)((r0 + mt*16 + gr)     * A2_STR + col) * 2;
                const uint32_t r1b = (uint32_t)((r0 + mt*16 + gr + 8) * A2_STR + col) * 2;
                *(uint32_t*)(smem + OFF_A2HI + r0b) = hp0;
                *(uint32_t*)(smem + OFF_A2LO + r0b) = lp0;
                *(uint32_t*)(smem + OFF_A2HI + r1b) = hp1;
                *(uint32_t*)(smem + OFF_A2LO + r1b) = lp1;
                c[mt][nt][0]=0.f; c[mt][nt][1]=0.f; c[mt][nt][2]=0.f; c[mt][nt][3]=0.f;
            }
        }
        BAR_GRP(1 + wm);   // A2 rows of this group complete

        // -------- GEMM2: [32x128] x W2[:,d0:d0+32]  (a_hi + a_lo) x b_hi --------
        #pragma unroll
        for (int k = 0; k < 8; k++) {
            uint32_t ah[2][4], al[2][4];
            #pragma unroll
            for (int mt = 0; mt < 2; mt++) {
                const uint32_t ab = (uint32_t)((r0 + mt*16 + arow) * A2_STR + k*16 + acol) * 2;
                LDSM_X4(ah[mt], sb + OFF_A2HI + ab);
                LDSM_X4(al[mt], sb + OFF_A2LO + ab);
            }
            const uint32_t brow = (uint32_t)((k*16 + arow) * W_STR + d0 + acol) * 2;
            #pragma unroll
            for (int p = 0; p < 2; p++) {
                uint32_t bh[4];
                LDSM_X4T(bh, sb + OFF_W2H + brow + (uint32_t)(p * 16) * 2);
                #pragma unroll
                for (int q = 0; q < 2; q++)
                    #pragma unroll
                    for (int mt = 0; mt < 2; mt++)
                        MMA_F16(c[mt][2*p+q], ah[mt], bh[2*q], bh[2*q+1]);
                #pragma unroll
                for (int q = 0; q < 2; q++)
                    #pragma unroll
                    for (int mt = 0; mt < 2; mt++)
                        MMA_F16(c[mt][2*p+q], al[mt], bh[2*q], bh[2*q+1]);
            }
        }
        __syncthreads();   // ALL A2 reads done before fbuf (A2 overlay) writes

        // -------- Epilogue 2: +b2, ssp -> fbuf (fp32, overlays A2) --------
        #pragma unroll
        for (int mt = 0; mt < 2; mt++) {
            #pragma unroll
            for (int nt = 0; nt < 4; nt++) {
                const int col = d0 + nt*8 + cc;
                const float f0 = ssp(c[mt][nt][0] + b2s[col]);
                const float f1 = ssp(c[mt][nt][1] + b2s[col + 1]);
                const float f2 = ssp(c[mt][nt][2] + b2s[col]);
                const float f3 = ssp(c[mt][nt][3] + b2s[col + 1]);
                *(float2*)&fb[(r0 + mt*16 + gr)     * FB_STR + col] = make_float2(f0, f1);
                *(float2*)&fb[(r0 + mt*16 + gr + 8) * FB_STR + col] = make_float2(f2, f3);
            }
        }
        __syncthreads();

        // -------- Overlap: RBF(next tile) -> A1  ||  gather(g) from fbuf --------
        const int gnext = g + gridDim.x;
        if (gnext < total) rbf_phase(gnext, parity ^ 1);

        {
            const int2* ems = (const int2*)(smem + OFF_EMS) + parity * 128;
            const int ch = (tid & 63) * 2;      // channel pair
            const int sp = tid >> 6;            // span 0..7 (16 edges each)
            const float* AFp = AF + (size_t)b * N * D_DIM;
            float*       Op  = out + (size_t)b * N * D_DIM;
            int cur = -1; float2 acc = make_float2(0.f, 0.f);
            const int e_beg = sp * 16;

            if (ne == TILE_M) {
                #pragma unroll
                for (int chk = 0; chk < 2; chk++) {
                    const int eb = e_beg + chk * 8;
                    float2 m[8]; int sr[8];
                    #pragma unroll
                    for (int e = 0; e < 8; e++) {
                        const int2 js = ems[eb + e];
                        sr[e] = js.y;
                        const float2 af = *(const float2*)&AFp[(size_t)js.x * D_DIM + ch];
                        const float2 f  = *(const float2*)&fb[(eb + e) * FB_STR + ch];
                        m[e] = make_float2(af.x * f.x, af.y * f.y);
                    }
                    #pragma unroll
                    for (int e = 0; e < 8; e++) {
                        if (sr[e] != cur) {
                            if (cur >= 0) {
                                atomicAdd(&Op[(size_t)cur * D_DIM + ch],     acc.x);
                                atomicAdd(&Op[(size_t)cur * D_DIM + ch + 1], acc.y);
                            }
                            cur = sr[e]; acc = m[e];
                        } else { acc.x += m[e].x; acc.y += m[e].y; }
                    }
                }
            } else {
                const int e_end = min(e_beg + 16, ne);
                for (int e = e_beg; e < e_end; e++) {
                    const int2 js = ems[e];
                    const float2 af = *(const float2*)&AFp[(size_t)js.x * D_DIM + ch];
                    const float2 f  = *(const float2*)&fb[e * FB_STR + ch];
                    const float2 m  = make_float2(af.x * f.x, af.y * f.y);
                    if (js.y != cur) {
                        if (cur >= 0) {
                            atomicAdd(&Op[(size_t)cur * D_DIM + ch],     acc.x);
                            atomicAdd(&Op[(size_t)cur * D_DIM + ch + 1], acc.y);
                        }
                        cur = js.y; acc = m;
                    } else { acc.x += m.x; acc.y += m.y; }
                }
            }
            if (cur >= 0) {
                atomicAdd(&Op[(size_t)cur * D_DIM + ch],     acc.x);
                atomicAdd(&Op[(size_t)cur * D_DIM + ch + 1], acc.y);
            }
        }
        parity ^= 1;
        __syncthreads();   // gather done (fbuf free) & A1 ready for next GEMM1
    }
}

extern "C" void kernel_launch(void* const* d_in, const int* in_sizes, int n_in,
                              void* d_out, int out_size) {
    // order: atom_features, distances, idx_j, seg_i, centers, gamma, W1, b1, W2, b2
    const float* AF      = (const float*)d_in[0];
    const float* dist    = (const float*)d_in[1];
    const int*   idx_j   = (const int*)  d_in[2];
    const int*   seg_i   = (const int*)  d_in[3];
    const float* centers = (const float*)d_in[4];
    const float* gamma   = (const float*)d_in[5];
    const float* W1      = (const float*)d_in[6];
    const float* b1      = (const float*)d_in[7];
    const float* W2      = (const float*)d_in[8];
    const float* b2      = (const float*)d_in[9];
    float* out = (float*)d_out;

    const int E = in_sizes[2];
    const int B = in_sizes[1] / E;
    const int D = in_sizes[7];              // 128
    const int N = in_sizes[0] / (B * D);

    zero_out_kernel<<<2048, 256>>>(out, (size_t)out_size);

    cudaFuncSetAttribute(cfconv_mma_kernel,
                         cudaFuncAttributeMaxDynamicSharedMemorySize, SMEM_TOTAL);
    cfconv_mma_kernel<<<148, THREADS, SMEM_TOTAL>>>(
        AF, dist, idx_j, seg_i, W1, b1, W2, b2, centers, gamma, out, B, N, E);
}

// round 12
// speedup vs baseline: 1.5387x; 1.2986x over previous
#include <cuda_runtime.h>
#include <cuda_fp16.h>
#include <cstdint>

#define THREADS 512
#define TILE_M  128
#define D_DIM   128
#define K_RBF   64

// strides in fp16 elements
#define W_STR   136      // 128 + 8 pad
#define A1_STR  72       // 64 + 8 pad
#define A2_STR  136
#define FB_STR  130      // halves per fbuf row (128 + 2 pad)

// ---------------- smem layout (bytes) ----------------
#define OFF_W1H  0
#define OFF_W2H  (OFF_W1H + K_RBF * W_STR * 2)        // 17408
#define OFF_A1   (OFF_W2H + D_DIM * W_STR * 2)        // 52224
#define OFF_A2   (OFF_A1 + TILE_M * A1_STR * 2)       // 70656
#define OFF_FBUF OFF_A2                                // fp16 fbuf (33280 <= 34816)
#define OFF_B1S  (OFF_A2 + TILE_M * A2_STR * 2)       // 105472
#define OFF_B2S  (OFF_B1S + 512)
#define OFF_CEN  (OFF_B2S + 512)
#define OFF_GAM  (OFF_CEN + 256)
#define OFF_EMS  (OFF_GAM + 256)                       // int2[2][128]
#define SMEM_TOTAL (OFF_EMS + 2048)                    // 109056

// ---------------- PTX helpers ----------------
static __device__ __forceinline__ uint32_t smem_u32(const void* p) {
    uint32_t a;
    asm("{ .reg .u64 t; cvta.to.shared.u64 t, %1; cvt.u32.u64 %0, t; }" : "=r"(a) : "l"(p));
    return a;
}

#define BAR_GRP(id) asm volatile("bar.sync %0, %1;" :: "r"(id), "r"(128) : "memory")

#define LDSM_X4(r, addr)                                                     \
    asm volatile("ldmatrix.sync.aligned.m8n8.x4.shared.b16 {%0,%1,%2,%3}, [%4];" \
        : "=r"((r)[0]), "=r"((r)[1]), "=r"((r)[2]), "=r"((r)[3]) : "r"(addr))

#define LDSM_X4T(r, addr)                                                    \
    asm volatile("ldmatrix.sync.aligned.m8n8.x4.trans.shared.b16 {%0,%1,%2,%3}, [%4];" \
        : "=r"((r)[0]), "=r"((r)[1]), "=r"((r)[2]), "=r"((r)[3]) : "r"(addr))

#define MMA_F16(c, a, b0, b1)                                                \
    asm("mma.sync.aligned.m16n8k16.row.col.f32.f16.f16.f32 "                \
        "{%0,%1,%2,%3}, {%4,%5,%6,%7}, {%8,%9}, {%0,%1,%2,%3};"             \
        : "+f"((c)[0]), "+f"((c)[1]), "+f"((c)[2]), "+f"((c)[3])            \
        : "r"((a)[0]), "r"((a)[1]), "r"((a)[2]), "r"((a)[3]),               \
          "r"(b0), "r"(b1))

static __device__ __forceinline__ float ssp(float x) {
    return fmaxf(x, 0.f) + __logf(1.f + __expf(-fabsf(x))) - 0.69314718055994531f;
}

static __device__ __forceinline__ uint32_t pack_f16x2(float f0, float f1) {
    uint32_t r;
    asm("cvt.rn.f16x2.f32 %0, %1, %2;" : "=r"(r) : "f"(f1), "f"(f0));
    return r;
}

__global__ void zero_out_kernel(float* __restrict__ out, size_t n) {
    size_t i = (size_t)blockIdx.x * blockDim.x + threadIdx.x;
    size_t stride = (size_t)gridDim.x * blockDim.x;
    for (; i < n; i += stride) out[i] = 0.f;
}

extern __shared__ char smem[];

__global__ void __launch_bounds__(THREADS, 1)
cfconv_mma_kernel(const float* __restrict__ AF,     // [B,N,D]
                  const float* __restrict__ dist,   // [B,E]
                  const int*   __restrict__ idx_j,  // [E]
                  const int*   __restrict__ seg_i,  // [E] sorted
                  const float* __restrict__ W1,     // [K,D]
                  const float* __restrict__ b1,
                  const float* __restrict__ W2,     // [D,D]
                  const float* __restrict__ b2,
                  const float* __restrict__ centers,
                  const float* __restrict__ gamma,
                  float* __restrict__ out,          // [B,N,D]
                  int B, int N, int E)
{
    const uint32_t sb = smem_u32(smem);
    const int tid  = threadIdx.x;
    const int w    = tid >> 5;
    const int lane = tid & 31;

    float*  b1s = (float*)(smem + OFF_B1S);
    float*  b2s = (float*)(smem + OFF_B2S);
    float*  cen = (float*)(smem + OFF_CEN);
    float*  gam = (float*)(smem + OFF_GAM);
    __half* fb  = (__half*)(smem + OFF_FBUF);

    // ---- weight prep: fp16, padded row-major [K][D] ----
    for (int i = tid; i < K_RBF * D_DIM; i += THREADS) {
        const int k = i >> 7, d = i & 127;
        *(__half*)(smem + OFF_W1H + (k * W_STR + d) * 2) = __float2half_rn(W1[i]);
    }
    for (int i = tid; i < D_DIM * D_DIM; i += THREADS) {
        const int k = i >> 7, d = i & 127;
        *(__half*)(smem + OFF_W2H + (k * W_STR + d) * 2) = __float2half_rn(W2[i]);
    }
    if (tid < D_DIM) { b1s[tid] = b1[tid]; b2s[tid] = b2[tid]; }
    if (tid >= 128 && tid < 128 + K_RBF) {
        const int k = tid - 128; cen[k] = centers[k]; gam[k] = gamma[k];
    }
    __syncthreads();

    // warp tiling: 4x4 warp grid, each warp owns 32 edges x 32 cols
    const int wm = w & 3;              // row group (barrier id 1+wm)
    const int wn = w >> 2;             // col group
    const int r0 = wm * 32;
    const int d0 = wn * 32;
    const int arow = lane & 15;
    const int acol = (lane >> 4) * 8;
    const int gr   = lane >> 2;
    const int cc   = (lane & 3) * 2;

    const int tiles_pb = (E + TILE_M - 1) / TILE_M;
    const int total    = B * tiles_pb;

    // RBF phase for a tile: writes A1 + meta (ems[par])
    auto rbf_phase = [&](int gidx, int par) {
        const int bb_ = gidx / tiles_pb;
        const int e0_ = (gidx - bb_ * tiles_pb) * TILE_M;
        const int ne_ = min(TILE_M, E - e0_);
        const float* db_ = dist + (size_t)bb_ * E;
        const int el = r0 + lane;             // own group's edge row
        const int kb = wn * 16;
        const int eg = e0_ + min(el, ne_ - 1);
        const float dv = __ldg(&db_[eg]);
        #pragma unroll
        for (int kk = 0; kk < 16; kk += 2) {
            const int k = kb + kk;
            const float t0 = dv - cen[k];
            const float t1 = dv - cen[k + 1];
            const float v0 = __expf(-gam[k]     * t0 * t0);
            const float v1 = __expf(-gam[k + 1] * t1 * t1);
            const uint32_t byt = (uint32_t)(el * A1_STR + k) * 2;
            *(uint32_t*)(smem + OFF_A1 + byt) = pack_f16x2(v0, v1);
        }
        if (tid < TILE_M) {
            const int e = e0_ + min(tid, ne_ - 1);
            ((int2*)(smem + OFF_EMS))[par * 128 + tid] =
                make_int2(__ldg(&idx_j[e]), __ldg(&seg_i[e]));
        }
    };

    int parity = 0;
    const int g0 = blockIdx.x;
    if (g0 < total) rbf_phase(g0, parity);
    __syncthreads();

    for (int g = g0; g < total; g += gridDim.x) {
        const int b  = g / tiles_pb;
        const int e0 = (g - b * tiles_pb) * TILE_M;
        const int ne = min(TILE_M, E - e0);

        float c[2][4][4];
        #pragma unroll
        for (int mt = 0; mt < 2; mt++)
            #pragma unroll
            for (int nt = 0; nt < 4; nt++)
                { c[mt][nt][0]=0.f; c[mt][nt][1]=0.f; c[mt][nt][2]=0.f; c[mt][nt][3]=0.f; }

        // -------- GEMM1: [32x64] x W1[:,d0:d0+32] --------
        #pragma unroll
        for (int k = 0; k < 4; k++) {
            uint32_t a[2][4];
            #pragma unroll
            for (int mt = 0; mt < 2; mt++) {
                const uint32_t ab = (uint32_t)((r0 + mt*16 + arow) * A1_STR + k*16 + acol) * 2;
                LDSM_X4(a[mt], sb + OFF_A1 + ab);
            }
            const uint32_t brow = (uint32_t)((k*16 + arow) * W_STR + d0 + acol) * 2;
            #pragma unroll
            for (int p = 0; p < 2; p++) {
                uint32_t bh[4];
                LDSM_X4T(bh, sb + OFF_W1H + brow + (uint32_t)(p * 16) * 2);
                #pragma unroll
                for (int q = 0; q < 2; q++)
                    #pragma unroll
                    for (int mt = 0; mt < 2; mt++)
                        MMA_F16(c[mt][2*p+q], a[mt], bh[2*q], bh[2*q+1]);
            }
        }

        // -------- Epilogue 1: +b1, ssp, fp16 -> A2 --------
        #pragma unroll
        for (int mt = 0; mt < 2; mt++) {
            #pragma unroll
            for (int nt = 0; nt < 4; nt++) {
                const int col = d0 + nt*8 + cc;
                const float f0 = ssp(c[mt][nt][0] + b1s[col]);
                const float f1 = ssp(c[mt][nt][1] + b1s[col + 1]);
                const float f2 = ssp(c[mt][nt][2] + b1s[col]);
                const float f3 = ssp(c[mt][nt][3] + b1s[col + 1]);
                const uint32_t r0b = (uint32_t)((r0 + mt*16 + gr)     * A2_STR + col) * 2;
                const uint32_t r1b = (uint32_t)((r0 + mt*16 + gr + 8) * A2_STR + col) * 2;
                *(uint32_t*)(smem + OFF_A2 + r0b) = pack_f16x2(f0, f1);
                *(uint32_t*)(smem + OFF_A2 + r1b) = pack_f16x2(f2, f3);
                c[mt][nt][0]=0.f; c[mt][nt][1]=0.f; c[mt][nt][2]=0.f; c[mt][nt][3]=0.f;
            }
        }
        BAR_GRP(1 + wm);   // A2 rows of this group complete

        // -------- GEMM2: [32x128] x W2[:,d0:d0+32] --------
        #pragma unroll
        for (int k = 0; k < 8; k++) {
            uint32_t a[2][4];
            #pragma unroll
            for (int mt = 0; mt < 2; mt++) {
                const uint32_t ab = (uint32_t)((r0 + mt*16 + arow) * A2_STR + k*16 + acol) * 2;
                LDSM_X4(a[mt], sb + OFF_A2 + ab);
            }
            const uint32_t brow = (uint32_t)((k*16 + arow) * W_STR + d0 + acol) * 2;
            #pragma unroll
            for (int p = 0; p < 2; p++) {
                uint32_t bh[4];
                LDSM_X4T(bh, sb + OFF_W2H + brow + (uint32_t)(p * 16) * 2);
                #pragma unroll
                for (int q = 0; q < 2; q++)
                    #pragma unroll
                    for (int mt = 0; mt < 2; mt++)
                        MMA_F16(c[mt][2*p+q], a[mt], bh[2*q], bh[2*q+1]);
            }
        }
        __syncthreads();   // ALL A2 reads done before fbuf (A2 overlay) writes

        // -------- Epilogue 2: +b2, ssp -> fbuf (fp16, overlays A2) --------
        #pragma unroll
        for (int mt = 0; mt < 2; mt++) {
            #pragma unroll
            for (int nt = 0; nt < 4; nt++) {
                const int col = d0 + nt*8 + cc;
                const float f0 = ssp(c[mt][nt][0] + b2s[col]);
                const float f1 = ssp(c[mt][nt][1] + b2s[col + 1]);
                const float f2 = ssp(c[mt][nt][2] + b2s[col]);
                const float f3 = ssp(c[mt][nt][3] + b2s[col + 1]);
                *(uint32_t*)&fb[(r0 + mt*16 + gr)     * FB_STR + col] = pack_f16x2(f0, f1);
                *(uint32_t*)&fb[(r0 + mt*16 + gr + 8) * FB_STR + col] = pack_f16x2(f2, f3);
            }
        }
        __syncthreads();

        // -------- Overlap: RBF(next tile) -> A1  ||  gather(g) from fbuf --------
        const int gnext = g + gridDim.x;
        if (gnext < total) rbf_phase(gnext, parity ^ 1);

        {
            const int2* ems = (const int2*)(smem + OFF_EMS) + parity * 128;
            const int ch = (tid & 63) * 2;      // channel pair
            const int sp = tid >> 6;            // span 0..7 (16 edges each)
            const float* AFp = AF + (size_t)b * N * D_DIM;
            float*       Op  = out + (size_t)b * N * D_DIM;
            int cur = -1; float2 acc = make_float2(0.f, 0.f);
            const int e_beg = sp * 16;

            if (ne == TILE_M) {
                #pragma unroll
                for (int chk = 0; chk < 2; chk++) {
                    const int eb = e_beg + chk * 8;
                    float2 m[8]; int sr[8];
                    #pragma unroll
                    for (int e = 0; e < 8; e++) {
                        const int2 js = ems[eb + e];
                        sr[e] = js.y;
                        const float2 af = *(const float2*)&AFp[(size_t)js.x * D_DIM + ch];
                        const float2 f  = __half22float2(*(const __half2*)&fb[(eb + e) * FB_STR + ch]);
                        m[e] = make_float2(af.x * f.x, af.y * f.y);
                    }
                    #pragma unroll
                    for (int e = 0; e < 8; e++) {
                        if (sr[e] != cur) {
                            if (cur >= 0) {
                                atomicAdd(&Op[(size_t)cur * D_DIM + ch],     acc.x);
                                atomicAdd(&Op[(size_t)cur * D_DIM + ch + 1], acc.y);
                            }
                            cur = sr[e]; acc = m[e];
                        } else { acc.x += m[e].x; acc.y += m[e].y; }
                    }
                }
            } else {
                const int e_end = min(e_beg + 16, ne);
                for (int e = e_beg; e < e_end; e++) {
                    const int2 js = ems[e];
                    const float2 af = *(const float2*)&AFp[(size_t)js.x * D_DIM + ch];
                    const float2 f  = __half22float2(*(const __half2*)&fb[e * FB_STR + ch]);
                    const float2 m  = make_float2(af.x * f.x, af.y * f.y);
                    if (js.y != cur) {
                        if (cur >= 0) {
                            atomicAdd(&Op[(size_t)cur * D_DIM + ch],     acc.x);
                            atomicAdd(&Op[(size_t)cur * D_DIM + ch + 1], acc.y);
                        }
                        cur = js.y; acc = m;
                    } else { acc.x += m.x; acc.y += m.y; }
                }
            }
            if (cur >= 0) {
                atomicAdd(&Op[(size_t)cur * D_DIM + ch],     acc.x);
                atomicAdd(&Op[(size_t)cur * D_DIM + ch + 1], acc.y);
            }
        }
        parity ^= 1;
        __syncthreads();   // gather done (fbuf free) & A1 ready for next GEMM1
    }
}

extern "C" void kernel_launch(void* const* d_in, const int* in_sizes, int n_in,
                              void* d_out, int out_size) {
    // order: atom_features, distances, idx_j, seg_i, centers, gamma, W1, b1, W2, b2
    const float* AF      = (const float*)d_in[0];
    const float* dist    = (const float*)d_in[1];
    const int*   idx_j   = (const int*)  d_in[2];
    const int*   seg_i   = (const int*)  d_in[3];
    const float* centers = (const float*)d_in[4];
    const float* gamma   = (const float*)d_in[5];
    const float* W1      = (const float*)d_in[6];
    const float* b1      = (const float*)d_in[7];
    const float* W2      = (const float*)d_in[8];
    const float* b2      = (const float*)d_in[9];
    float* out = (float*)d_out;

    const int E = in_sizes[2];
    const int B = in_sizes[1] / E;
    const int D = in_sizes[7];              // 128
    const int N = in_sizes[0] / (B * D);

    zero_out_kernel<<<2048, 256>>>(out, (size_t)out_size);

    cudaFuncSetAttribute(cfconv_mma_kernel,
                         cudaFuncAttributeMaxDynamicSharedMemorySize, SMEM_TOTAL);
    cfconv_mma_kernel<<<148, THREADS, SMEM_TOTAL>>>(
        AF, dist, idx_j, seg_i, W1, b1, W2, b2, centers, gamma, out, B, N, E);
}

// round 13
// speedup vs baseline: 1.6351x; 1.0626x over previous
#include <cuda_runtime.h>
#include <cuda_fp16.h>
#include <cstdint>

#define THREADS 256
#define TILE_M  64
#define D_DIM   128
#define K_RBF   64

// strides in fp16 elements
#define W_STR   136      // 128 + 8 pad
#define A1_STR  72       // 64 + 8 pad
#define A2_STR  136
#define FB_STR  130      // halves per fbuf row

// ---------------- smem layout (bytes) ----------------
#define OFF_W1H  0
#define OFF_W2H  (OFF_W1H + K_RBF * W_STR * 2)        // 17408
#define OFF_A1   (OFF_W2H + D_DIM * W_STR * 2)        // 52224
#define OFF_A2   (OFF_A1 + TILE_M * A1_STR * 2)       // 61440
#define OFF_FBUF OFF_A2                                // fp16 fbuf (16640 <= 17408)
#define OFF_B1S  (OFF_A2 + TILE_M * A2_STR * 2)       // 78848
#define OFF_B2S  (OFF_B1S + 512)
#define OFF_CEN  (OFF_B2S + 512)
#define OFF_GAM  (OFF_CEN + 256)
#define OFF_EMS  (OFF_GAM + 256)                       // int2[2][64]
#define SMEM_TOTAL (OFF_EMS + 1024)                    // 81408 -> 2 CTAs/SM

// ---------------- PTX helpers ----------------
static __device__ __forceinline__ uint32_t smem_u32(const void* p) {
    uint32_t a;
    asm("{ .reg .u64 t; cvta.to.shared.u64 t, %1; cvt.u32.u64 %0, t; }" : "=r"(a) : "l"(p));
    return a;
}

#define BAR_GRP(id) asm volatile("bar.sync %0, %1;" :: "r"(id), "r"(128) : "memory")

#define LDSM_X4(r, addr)                                                     \
    asm volatile("ldmatrix.sync.aligned.m8n8.x4.shared.b16 {%0,%1,%2,%3}, [%4];" \
        : "=r"((r)[0]), "=r"((r)[1]), "=r"((r)[2]), "=r"((r)[3]) : "r"(addr))

#define LDSM_X4T(r, addr)                                                    \
    asm volatile("ldmatrix.sync.aligned.m8n8.x4.trans.shared.b16 {%0,%1,%2,%3}, [%4];" \
        : "=r"((r)[0]), "=r"((r)[1]), "=r"((r)[2]), "=r"((r)[3]) : "r"(addr))

#define MMA_F16(c, a, b0, b1)                                                \
    asm("mma.sync.aligned.m16n8k16.row.col.f32.f16.f16.f32 "                \
        "{%0,%1,%2,%3}, {%4,%5,%6,%7}, {%8,%9}, {%0,%1,%2,%3};"             \
        : "+f"((c)[0]), "+f"((c)[1]), "+f"((c)[2]), "+f"((c)[3])            \
        : "r"((a)[0]), "r"((a)[1]), "r"((a)[2]), "r"((a)[3]),               \
          "r"(b0), "r"(b1))

static __device__ __forceinline__ float ssp(float x) {
    return fmaxf(x, 0.f) + __logf(1.f + __expf(-fabsf(x))) - 0.69314718055994531f;
}

static __device__ __forceinline__ uint32_t pack_f16x2(float f0, float f1) {
    uint32_t r;
    asm("cvt.rn.f16x2.f32 %0, %1, %2;" : "=r"(r) : "f"(f1), "f"(f0));
    return r;
}

__global__ void zero_out_kernel(float* __restrict__ out, size_t n) {
    size_t i = (size_t)blockIdx.x * blockDim.x + threadIdx.x;
    size_t stride = (size_t)gridDim.x * blockDim.x;
    for (; i < n; i += stride) out[i] = 0.f;
}

extern __shared__ char smem[];

__global__ void __launch_bounds__(THREADS, 2)
cfconv_mma_kernel(const float* __restrict__ AF,     // [B,N,D]
                  const float* __restrict__ dist,   // [B,E]
                  const int*   __restrict__ idx_j,  // [E]
                  const int*   __restrict__ seg_i,  // [E] sorted
                  const float* __restrict__ W1,     // [K,D]
                  const float* __restrict__ b1,
                  const float* __restrict__ W2,     // [D,D]
                  const float* __restrict__ b2,
                  const float* __restrict__ centers,
                  const float* __restrict__ gamma,
                  float* __restrict__ out,          // [B,N,D]
                  int B, int N, int E)
{
    const uint32_t sb = smem_u32(smem);
    const int tid  = threadIdx.x;
    const int w    = tid >> 5;
    const int lane = tid & 31;

    float*  b1s = (float*)(smem + OFF_B1S);
    float*  b2s = (float*)(smem + OFF_B2S);
    float*  cen = (float*)(smem + OFF_CEN);
    float*  gam = (float*)(smem + OFF_GAM);
    __half* fb  = (__half*)(smem + OFF_FBUF);

    // ---- weight prep: fp16, padded row-major [K][D] ----
    for (int i = tid; i < K_RBF * D_DIM; i += THREADS) {
        const int k = i >> 7, d = i & 127;
        *(__half*)(smem + OFF_W1H + (k * W_STR + d) * 2) = __float2half_rn(W1[i]);
    }
    for (int i = tid; i < D_DIM * D_DIM; i += THREADS) {
        const int k = i >> 7, d = i & 127;
        *(__half*)(smem + OFF_W2H + (k * W_STR + d) * 2) = __float2half_rn(W2[i]);
    }
    if (tid < D_DIM) { b1s[tid] = b1[tid]; b2s[tid] = b2[tid]; }
    else if (tid >= 128 && tid < 128 + K_RBF) {
        const int k = tid - 128; cen[k] = centers[k]; gam[k] = gamma[k];
    }
    __syncthreads();

    // warp tiling: 2x4 warp grid, each warp owns 32 edges x 32 cols
    const int wm = w & 1;              // row group (barrier id 1+wm, 128 threads)
    const int wn = w >> 1;             // col group 0..3
    const int r0 = wm * 32;
    const int d0 = wn * 32;
    const int arow = lane & 15;
    const int acol = (lane >> 4) * 8;
    const int gr   = lane >> 2;
    const int cc   = (lane & 3) * 2;

    const int tiles_pb = (E + TILE_M - 1) / TILE_M;
    const int total    = B * tiles_pb;

    // RBF phase for a tile: writes A1 rows [r0,r0+32) + meta (ems[par])
    auto rbf_phase = [&](int gidx, int par) {
        const int bb_ = gidx / tiles_pb;
        const int e0_ = (gidx - bb_ * tiles_pb) * TILE_M;
        const int ne_ = min(TILE_M, E - e0_);
        const float* db_ = dist + (size_t)bb_ * E;
        const int el = r0 + lane;             // own group's edge row
        const int kb = wn * 16;
        const int eg = e0_ + min(el, ne_ - 1);
        const float dv = __ldg(&db_[eg]);
        #pragma unroll
        for (int kk = 0; kk < 16; kk += 2) {
            const int k = kb + kk;
            const float t0 = dv - cen[k];
            const float t1 = dv - cen[k + 1];
            const float v0 = __expf(-gam[k]     * t0 * t0);
            const float v1 = __expf(-gam[k + 1] * t1 * t1);
            const uint32_t byt = (uint32_t)(el * A1_STR + k) * 2;
            *(uint32_t*)(smem + OFF_A1 + byt) = pack_f16x2(v0, v1);
        }
        if (tid < TILE_M) {
            const int e = e0_ + min(tid, ne_ - 1);
            ((int2*)(smem + OFF_EMS))[par * TILE_M + tid] =
                make_int2(__ldg(&idx_j[e]), __ldg(&seg_i[e]));
        }
    };

    int parity = 0;
    const int g0 = blockIdx.x;
    if (g0 < total) rbf_phase(g0, parity);
    __syncthreads();

    for (int g = g0; g < total; g += gridDim.x) {
        const int b  = g / tiles_pb;
        const int e0 = (g - b * tiles_pb) * TILE_M;
        const int ne = min(TILE_M, E - e0);

        float c[2][4][4];
        #pragma unroll
        for (int mt = 0; mt < 2; mt++)
            #pragma unroll
            for (int nt = 0; nt < 4; nt++)
                { c[mt][nt][0]=0.f; c[mt][nt][1]=0.f; c[mt][nt][2]=0.f; c[mt][nt][3]=0.f; }

        // -------- GEMM1: [32x64] x W1[:,d0:d0+32] --------
        #pragma unroll
        for (int k = 0; k < 4; k++) {
            uint32_t a[2][4];
            #pragma unroll
            for (int mt = 0; mt < 2; mt++) {
                const uint32_t ab = (uint32_t)((r0 + mt*16 + arow) * A1_STR + k*16 + acol) * 2;
                LDSM_X4(a[mt], sb + OFF_A1 + ab);
            }
            const uint32_t brow = (uint32_t)((k*16 + arow) * W_STR + d0 + acol) * 2;
            #pragma unroll
            for (int p = 0; p < 2; p++) {
                uint32_t bh[4];
                LDSM_X4T(bh, sb + OFF_W1H + brow + (uint32_t)(p * 16) * 2);
                #pragma unroll
                for (int q = 0; q < 2; q++)
                    #pragma unroll
                    for (int mt = 0; mt < 2; mt++)
                        MMA_F16(c[mt][2*p+q], a[mt], bh[2*q], bh[2*q+1]);
            }
        }

        // -------- Epilogue 1: +b1, ssp, fp16 -> A2 --------
        #pragma unroll
        for (int mt = 0; mt < 2; mt++) {
            #pragma unroll
            for (int nt = 0; nt < 4; nt++) {
                const int col = d0 + nt*8 + cc;
                const float f0 = ssp(c[mt][nt][0] + b1s[col]);
                const float f1 = ssp(c[mt][nt][1] + b1s[col + 1]);
                const float f2 = ssp(c[mt][nt][2] + b1s[col]);
                const float f3 = ssp(c[mt][nt][3] + b1s[col + 1]);
                const uint32_t r0b = (uint32_t)((r0 + mt*16 + gr)     * A2_STR + col) * 2;
                const uint32_t r1b = (uint32_t)((r0 + mt*16 + gr + 8) * A2_STR + col) * 2;
                *(uint32_t*)(smem + OFF_A2 + r0b) = pack_f16x2(f0, f1);
                *(uint32_t*)(smem + OFF_A2 + r1b) = pack_f16x2(f2, f3);
                c[mt][nt][0]=0.f; c[mt][nt][1]=0.f; c[mt][nt][2]=0.f; c[mt][nt][3]=0.f;
            }
        }
        BAR_GRP(1 + wm);   // A2 rows of this group complete

        // -------- GEMM2: [32x128] x W2[:,d0:d0+32] --------
        #pragma unroll
        for (int k = 0; k < 8; k++) {
            uint32_t a[2][4];
            #pragma unroll
            for (int mt = 0; mt < 2; mt++) {
                const uint32_t ab = (uint32_t)((r0 + mt*16 + arow) * A2_STR + k*16 + acol) * 2;
                LDSM_X4(a[mt], sb + OFF_A2 + ab);
            }
            const uint32_t brow = (uint32_t)((k*16 + arow) * W_STR + d0 + acol) * 2;
            #pragma unroll
            for (int p = 0; p < 2; p++) {
                uint32_t bh[4];
                LDSM_X4T(bh, sb + OFF_W2H + brow + (uint32_t)(p * 16) * 2);
                #pragma unroll
                for (int q = 0; q < 2; q++)
                    #pragma unroll
                    for (int mt = 0; mt < 2; mt++)
                        MMA_F16(c[mt][2*p+q], a[mt], bh[2*q], bh[2*q+1]);
            }
        }
        __syncthreads();   // ALL A2 reads done before fbuf (A2 overlay) writes

        // -------- Epilogue 2: +b2, ssp -> fbuf (fp16, overlays A2) --------
        #pragma unroll
        for (int mt = 0; mt < 2; mt++) {
            #pragma unroll
            for (int nt = 0; nt < 4; nt++) {
                const int col = d0 + nt*8 + cc;
                const float f0 = ssp(c[mt][nt][0] + b2s[col]);
                const float f1 = ssp(c[mt][nt][1] + b2s[col + 1]);
                const float f2 = ssp(c[mt][nt][2] + b2s[col]);
                const float f3 = ssp(c[mt][nt][3] + b2s[col + 1]);
                *(uint32_t*)&fb[(r0 + mt*16 + gr)     * FB_STR + col] = pack_f16x2(f0, f1);
                *(uint32_t*)&fb[(r0 + mt*16 + gr + 8) * FB_STR + col] = pack_f16x2(f2, f3);
            }
        }
        __syncthreads();

        // -------- Overlap: RBF(next tile) -> A1  ||  gather(g) from fbuf --------
        const int gnext = g + gridDim.x;
        if (gnext < total) rbf_phase(gnext, parity ^ 1);

        {
            const int2* ems = (const int2*)(smem + OFF_EMS) + parity * TILE_M;
            const int ch = (tid & 63) * 2;      // channel pair
            const int sp = tid >> 6;            // span 0..3 (16 edges each)
            const float* AFp = AF + (size_t)b * N * D_DIM;
            float*       Op  = out + (size_t)b * N * D_DIM;
            int cur = -1; float2 acc = make_float2(0.f, 0.f);
            const int e_beg = sp * 16;

            if (ne == TILE_M) {
                #pragma unroll
                for (int chk = 0; chk < 2; chk++) {
                    const int eb = e_beg + chk * 8;
                    float2 m[8]; int sr[8];
                    #pragma unroll
                    for (int e = 0; e < 8; e++) {
                        const int2 js = ems[eb + e];
                        sr[e] = js.y;
                        const float2 af = *(const float2*)&AFp[(size_t)js.x * D_DIM + ch];
                        const float2 f  = __half22float2(*(const __half2*)&fb[(eb + e) * FB_STR + ch]);
                        m[e] = make_float2(af.x * f.x, af.y * f.y);
                    }
                    #pragma unroll
                    for (int e = 0; e < 8; e++) {
                        if (sr[e] != cur) {
                            if (cur >= 0) {
                                atomicAdd(&Op[(size_t)cur * D_DIM + ch],     acc.x);
                                atomicAdd(&Op[(size_t)cur * D_DIM + ch + 1], acc.y);
                            }
                            cur = sr[e]; acc = m[e];
                        } else { acc.x += m[e].x; acc.y += m[e].y; }
                    }
                }
            } else {
                const int e_end = min(e_beg + 16, ne);
                for (int e = e_beg; e < e_end; e++) {
                    const int2 js = ems[e];
                    const float2 af = *(const float2*)&AFp[(size_t)js.x * D_DIM + ch];
                    const float2 f  = __half22float2(*(const __half2*)&fb[e * FB_STR + ch]);
                    const float2 m  = make_float2(af.x * f.x, af.y * f.y);
                    if (js.y != cur) {
                        if (cur >= 0) {
                            atomicAdd(&Op[(size_t)cur * D_DIM + ch],     acc.x);
                            atomicAdd(&Op[(size_t)cur * D_DIM + ch + 1], acc.y);
                        }
                        cur = js.y; acc = m;
                    } else { acc.x += m.x; acc.y += m.y; }
                }
            }
            if (cur >= 0) {
                atomicAdd(&Op[(size_t)cur * D_DIM + ch],     acc.x);
                atomicAdd(&Op[(size_t)cur * D_DIM + ch + 1], acc.y);
            }
        }
        parity ^= 1;
        __syncthreads();   // gather done (fbuf free) & A1 ready for next GEMM1
    }
}

extern "C" void kernel_launch(void* const* d_in, const int* in_sizes, int n_in,
                              void* d_out, int out_size) {
    // order: atom_features, distances, idx_j, seg_i, centers, gamma, W1, b1, W2, b2
    const float* AF      = (const float*)d_in[0];
    const float* dist    = (const float*)d_in[1];
    const int*   idx_j   = (const int*)  d_in[2];
    const int*   seg_i   = (const int*)  d_in[3];
    const float* centers = (const float*)d_in[4];
    const float* gamma   = (const float*)d_in[5];
    const float* W1      = (const float*)d_in[6];
    const float* b1      = (const float*)d_in[7];
    const float* W2      = (const float*)d_in[8];
    const float* b2      = (const float*)d_in[9];
    float* out = (float*)d_out;

    const int E = in_sizes[2];
    const int B = in_sizes[1] / E;
    const int D = in_sizes[7];              // 128
    const int N = in_sizes[0] / (B * D);

    zero_out_kernel<<<2048, 256>>>(out, (size_t)out_size);

    cudaFuncSetAttribute(cfconv_mma_kernel,
                         cudaFuncAttributeMaxDynamicSharedMemorySize, SMEM_TOTAL);
    cfconv_mma_kernel<<<296, THREADS, SMEM_TOTAL>>>(
        AF, dist, idx_j, seg_i, W1, b1, W2, b2, centers, gamma, out, B, N, E);
}

// round 15
// speedup vs baseline: 1.6875x; 1.0321x over previous
#include <cuda_runtime.h>
#include <cuda_fp16.h>
#include <cstdint>

#define THREADS 256
#define TILE_M  64
#define D_DIM   128
#define K_RBF   64

// strides in fp16 elements
#define W_STR   136      // 128 + 8 pad
#define A1_STR  72       // 64 + 8 pad
#define A2_STR  136
#define FB_STR  130      // halves per fbuf row

// ---------------- smem layout (bytes) ----------------
#define OFF_W1H  0
#define OFF_W2H  (OFF_W1H + K_RBF * W_STR * 2)        // 17408
#define OFF_A1   (OFF_W2H + D_DIM * W_STR * 2)        // 52224
#define OFF_A2   (OFF_A1 + TILE_M * A1_STR * 2)       // 61440
#define OFF_FBUF OFF_A2                                // fp16 fbuf (16640 <= 17408)
#define OFF_B1S  (OFF_A2 + TILE_M * A2_STR * 2)       // 78848
#define OFF_B2S  (OFF_B1S + 512)
#define OFF_CEN  (OFF_B2S + 512)
#define OFF_GAM  (OFF_CEN + 256)
#define OFF_EMS  (OFF_GAM + 256)                       // int2[2][64]
#define SMEM_TOTAL (OFF_EMS + 1024)                    // 81408 -> 2 CTAs/SM

// ---------------- PTX helpers ----------------
static __device__ __forceinline__ uint32_t smem_u32(const void* p) {
    uint32_t a;
    asm("{ .reg .u64 t; cvta.to.shared.u64 t, %1; cvt.u32.u64 %0, t; }" : "=r"(a) : "l"(p));
    return a;
}

#define BAR_GRP(id) asm volatile("bar.sync %0, %1;" :: "r"(id), "r"(128) : "memory")

#define LDSM_X4(r, addr)                                                     \
    asm volatile("ldmatrix.sync.aligned.m8n8.x4.shared.b16 {%0,%1,%2,%3}, [%4];" \
        : "=r"((r)[0]), "=r"((r)[1]), "=r"((r)[2]), "=r"((r)[3]) : "r"(addr))

#define LDSM_X4T(r, addr)                                                    \
    asm volatile("ldmatrix.sync.aligned.m8n8.x4.trans.shared.b16 {%0,%1,%2,%3}, [%4];" \
        : "=r"((r)[0]), "=r"((r)[1]), "=r"((r)[2]), "=r"((r)[3]) : "r"(addr))

#define MMA_F16(c, a, b0, b1)                                                \
    asm("mma.sync.aligned.m16n8k16.row.col.f32.f16.f16.f32 "                \
        "{%0,%1,%2,%3}, {%4,%5,%6,%7}, {%8,%9}, {%0,%1,%2,%3};"             \
        : "+f"((c)[0]), "+f"((c)[1]), "+f"((c)[2]), "+f"((c)[3])            \
        : "r"((a)[0]), "r"((a)[1]), "r"((a)[2]), "r"((a)[3]),               \
          "r"(b0), "r"(b1))

// no-return vector reduction to global (sm_90+)
#define REDG_V2F32(addr, x, y)                                               \
    asm volatile("red.global.add.v2.f32 [%0], {%1, %2};"                    \
        :: "l"(addr), "f"(x), "f"(y) : "memory")

static __device__ __forceinline__ float ssp(float x) {
    return fmaxf(x, 0.f) + __logf(1.f + __expf(-fabsf(x))) - 0.69314718055994531f;
}

static __device__ __forceinline__ uint32_t pack_f16x2(float f0, float f1) {
    uint32_t r;
    asm("cvt.rn.f16x2.f32 %0, %1, %2;" : "=r"(r) : "f"(f1), "f"(f0));
    return r;
}

__global__ void zero_out_kernel(float* __restrict__ out, size_t n) {
    size_t i = (size_t)blockIdx.x * blockDim.x + threadIdx.x;
    size_t stride = (size_t)gridDim.x * blockDim.x;
    for (; i < n; i += stride) out[i] = 0.f;
}

extern __shared__ char smem[];

__global__ void __launch_bounds__(THREADS, 2)
cfconv_mma_kernel(const float* __restrict__ AF,     // [B,N,D]
                  const float* __restrict__ dist,   // [B,E]
                  const int*   __restrict__ idx_j,  // [E]
                  const int*   __restrict__ seg_i,  // [E] sorted
                  const float* __restrict__ W1,     // [K,D]
                  const float* __restrict__ b1,
                  const float* __restrict__ W2,     // [D,D]
                  const float* __restrict__ b2,
                  const float* __restrict__ centers,
                  const float* __restrict__ gamma,
                  float* __restrict__ out,          // [B,N,D]
                  int B, int N, int E)
{
    const uint32_t sb = smem_u32(smem);
    const int tid  = threadIdx.x;
    const int w    = tid >> 5;
    const int lane = tid & 31;

    float*  b1s = (float*)(smem + OFF_B1S);
    float*  b2s = (float*)(smem + OFF_B2S);
    float*  cen = (float*)(smem + OFF_CEN);
    float*  gam = (float*)(smem + OFF_GAM);
    __half* fb  = (__half*)(smem + OFF_FBUF);

    // ---- weight prep: fp16, padded row-major [K][D] ----
    for (int i = tid; i < K_RBF * D_DIM; i += THREADS) {
        const int k = i >> 7, d = i & 127;
        *(__half*)(smem + OFF_W1H + (k * W_STR + d) * 2) = __float2half_rn(W1[i]);
    }
    for (int i = tid; i < D_DIM * D_DIM; i += THREADS) {
        const int k = i >> 7, d = i & 127;
        *(__half*)(smem + OFF_W2H + (k * W_STR + d) * 2) = __float2half_rn(W2[i]);
    }
    if (tid < D_DIM) { b1s[tid] = b1[tid]; b2s[tid] = b2[tid]; }
    else if (tid >= 128 && tid < 128 + K_RBF) {
        const int k = tid - 128; cen[k] = centers[k]; gam[k] = gamma[k];
    }
    __syncthreads();

    // warp tiling: 2x4 warp grid, each warp owns 32 edges x 32 cols
    const int wm = w & 1;              // row group (barrier id 1+wm, 128 threads)
    const int wn = w >> 1;             // col group 0..3
    const int r0 = wm * 32;
    const int d0 = wn * 32;
    const int arow = lane & 15;
    const int acol = (lane >> 4) * 8;
    const int gr   = lane >> 2;
    const int cc   = (lane & 3) * 2;

    const int tiles_pb = (E + TILE_M - 1) / TILE_M;
    const int total    = B * tiles_pb;

    // RBF phase: cen/gam vector-preloaded; writes A1 rows [r0,r0+32) + meta
    auto rbf_phase = [&](int gidx, int par) {
        const int bb_ = gidx / tiles_pb;
        const int e0_ = (gidx - bb_ * tiles_pb) * TILE_M;
        const int ne_ = min(TILE_M, E - e0_);
        const float* db_ = dist + (size_t)bb_ * E;
        const int el = r0 + lane;             // own group's edge row
        const int kb = wn * 16;
        const int eg = e0_ + min(el, ne_ - 1);
        const float dv = __ldg(&db_[eg]);
        float c4[16], g4[16];
        #pragma unroll
        for (int i = 0; i < 4; i++) {
            *(float4*)&c4[i * 4] = *(const float4*)&cen[kb + i * 4];
            *(float4*)&g4[i * 4] = *(const float4*)&gam[kb + i * 4];
        }
        #pragma unroll
        for (int kk = 0; kk < 16; kk += 2) {
            const float t0 = dv - c4[kk];
            const float t1 = dv - c4[kk + 1];
            const float v0 = __expf(-g4[kk]     * t0 * t0);
            const float v1 = __expf(-g4[kk + 1] * t1 * t1);
            const uint32_t byt = (uint32_t)(el * A1_STR + kb + kk) * 2;
            *(uint32_t*)(smem + OFF_A1 + byt) = pack_f16x2(v0, v1);
        }
        if (tid < TILE_M) {
            const int e = e0_ + min(tid, ne_ - 1);
            ((int2*)(smem + OFF_EMS))[par * TILE_M + tid] =
                make_int2(__ldg(&idx_j[e]), __ldg(&seg_i[e]));
        }
    };

    int parity = 0;
    const int g0 = blockIdx.x;
    if (g0 < total) rbf_phase(g0, parity);
    __syncthreads();

    for (int g = g0; g < total; g += gridDim.x) {
        const int b  = g / tiles_pb;
        const int e0 = (g - b * tiles_pb) * TILE_M;
        const int ne = min(TILE_M, E - e0);

        float c[2][4][4];
        #pragma unroll
        for (int mt = 0; mt < 2; mt++)
            #pragma unroll
            for (int nt = 0; nt < 4; nt++)
                { c[mt][nt][0]=0.f; c[mt][nt][1]=0.f; c[mt][nt][2]=0.f; c[mt][nt][3]=0.f; }

        // -------- GEMM1: [32x64] x W1[:,d0:d0+32] --------
        #pragma unroll
        for (int k = 0; k < 4; k++) {
            uint32_t a[2][4];
            #pragma unroll
            for (int mt = 0; mt < 2; mt++) {
                const uint32_t ab = (uint32_t)((r0 + mt*16 + arow) * A1_STR + k*16 + acol) * 2;
                LDSM_X4(a[mt], sb + OFF_A1 + ab);
            }
            const uint32_t brow = (uint32_t)((k*16 + arow) * W_STR + d0 + acol) * 2;
            #pragma unroll
            for (int p = 0; p < 2; p++) {
                uint32_t bh[4];
                LDSM_X4T(bh, sb + OFF_W1H + brow + (uint32_t)(p * 16) * 2);
                #pragma unroll
                for (int q = 0; q < 2; q++)
                    #pragma unroll
                    for (int mt = 0; mt < 2; mt++)
                        MMA_F16(c[mt][2*p+q], a[mt], bh[2*q], bh[2*q+1]);
            }
        }

        // -------- Epilogue 1: +b1 (float2), ssp, fp16 -> A2 --------
        #pragma unroll
        for (int mt = 0; mt < 2; mt++) {
            #pragma unroll
            for (int nt = 0; nt < 4; nt++) {
                const int col = d0 + nt*8 + cc;
                const float2 bb = *(const float2*)&b1s[col];
                const float f0 = ssp(c[mt][nt][0] + bb.x);
                const float f1 = ssp(c[mt][nt][1] + bb.y);
                const float f2 = ssp(c[mt][nt][2] + bb.x);
                const float f3 = ssp(c[mt][nt][3] + bb.y);
                const uint32_t r0b = (uint32_t)((r0 + mt*16 + gr)     * A2_STR + col) * 2;
                const uint32_t r1b = (uint32_t)((r0 + mt*16 + gr + 8) * A2_STR + col) * 2;
                *(uint32_t*)(smem + OFF_A2 + r0b) = pack_f16x2(f0, f1);
                *(uint32_t*)(smem + OFF_A2 + r1b) = pack_f16x2(f2, f3);
                c[mt][nt][0]=0.f; c[mt][nt][1]=0.f; c[mt][nt][2]=0.f; c[mt][nt][3]=0.f;
            }
        }
        BAR_GRP(1 + wm);   // A2 rows of this group complete

        // -------- GEMM2: [32x128] x W2[:,d0:d0+32] --------
        #pragma unroll
        for (int k = 0; k < 8; k++) {
            uint32_t a[2][4];
            #pragma unroll
            for (int mt = 0; mt < 2; mt++) {
                const uint32_t ab = (uint32_t)((r0 + mt*16 + arow) * A2_STR + k*16 + acol) * 2;
                LDSM_X4(a[mt], sb + OFF_A2 + ab);
            }
            const uint32_t brow = (uint32_t)((k*16 + arow) * W_STR + d0 + acol) * 2;
            #pragma unroll
            for (int p = 0; p < 2; p++) {
                uint32_t bh[4];
                LDSM_X4T(bh, sb + OFF_W2H + brow + (uint32_t)(p * 16) * 2);
                #pragma unroll
                for (int q = 0; q < 2; q++)
                    #pragma unroll
                    for (int mt = 0; mt < 2; mt++)
                        MMA_F16(c[mt][2*p+q], a[mt], bh[2*q], bh[2*q+1]);
            }
        }
        __syncthreads();   // ALL A2 reads done before fbuf (A2 overlay) writes

        // -------- Epilogue 2: +b2 (float2), ssp -> fbuf (fp16) --------
        #pragma unroll
        for (int mt = 0; mt < 2; mt++) {
            #pragma unroll
            for (int nt = 0; nt < 4; nt++) {
                const int col = d0 + nt*8 + cc;
                const float2 bb = *(const float2*)&b2s[col];
                const float f0 = ssp(c[mt][nt][0] + bb.x);
                const float f1 = ssp(c[mt][nt][1] + bb.y);
                const float f2 = ssp(c[mt][nt][2] + bb.x);
                const float f3 = ssp(c[mt][nt][3] + bb.y);
                *(uint32_t*)&fb[(r0 + mt*16 + gr)     * FB_STR + col] = pack_f16x2(f0, f1);
                *(uint32_t*)&fb[(r0 + mt*16 + gr + 8) * FB_STR + col] = pack_f16x2(f2, f3);
            }
        }
        __syncthreads();

        // -------- Overlap: RBF(next tile) -> A1  ||  gather(g) from fbuf --------
        const int gnext = g + gridDim.x;
        if (gnext < total) rbf_phase(gnext, parity ^ 1);

        {
            const int2* ems = (const int2*)(smem + OFF_EMS) + parity * TILE_M;
            const int ch = (tid & 63) * 2;      // channel pair
            const int sp = tid >> 6;            // span 0..3 (16 edges each)
            const float* AFp = AF + (size_t)b * N * D_DIM;
            float*       Op  = out + (size_t)b * N * D_DIM;
            int cur = -1; float2 acc = make_float2(0.f, 0.f);
            const int e_beg = sp * 16;

            if (ne == TILE_M) {
                #pragma unroll
                for (int chk = 0; chk < 2; chk++) {
                    const int eb = e_beg + chk * 8;
                    float2 m[8]; int sr[8];
                    #pragma unroll
                    for (int e = 0; e < 8; e++) {
                        const int2 js = ems[eb + e];
                        sr[e] = js.y;
                        const float2 af = *(const float2*)&AFp[(size_t)js.x * D_DIM + ch];
                        const float2 f  = __half22float2(*(const __half2*)&fb[(eb + e) * FB_STR + ch]);
                        m[e] = make_float2(af.x * f.x, af.y * f.y);
                    }
                    #pragma unroll
                    for (int e = 0; e < 8; e++) {
                        if (sr[e] != cur) {
                            if (cur >= 0) REDG_V2F32(&Op[(size_t)cur * D_DIM + ch], acc.x, acc.y);
                            cur = sr[e]; acc = m[e];
                        } else { acc.x += m[e].x; acc.y += m[e].y; }
                    }
                }
            } else {
                const int e_end = min(e_beg + 16, ne);
                for (int e = e_beg; e < e_end; e++) {
                    const int2 js = ems[e];
                    const float2 af = *(const float2*)&AFp[(size_t)js.x * D_DIM + ch];
                    const float2 f  = __half22float2(*(const __half2*)&fb[e * FB_STR + ch]);
                    const float2 m  = make_float2(af.x * f.x, af.y * f.y);
                    if (js.y != cur) {
                        if (cur >= 0) REDG_V2F32(&Op[(size_t)cur * D_DIM + ch], acc.x, acc.y);
                        cur = js.y; acc = m;
                    } else { acc.x += m.x; acc.y += m.y; }
                }
            }
            if (cur >= 0) REDG_V2F32(&Op[(size_t)cur * D_DIM + ch], acc.x, acc.y);
        }
        parity ^= 1;
        __syncthreads();   // gather done (fbuf free) & A1 ready for next GEMM1
    }
}

extern "C" void kernel_launch(void* const* d_in, const int* in_sizes, int n_in,
                              void* d_out, int out_size) {
    // order: atom_features, distances, idx_j, seg_i, centers, gamma, W1, b1, W2, b2
    const float* AF      = (const float*)d_in[0];
    const float* dist    = (const float*)d_in[1];
    const int*   idx_j   = (const int*)  d_in[2];
    const int*   seg_i   = (const int*)  d_in[3];
    const float* centers = (const float*)d_in[4];
    const float* gamma   = (const float*)d_in[5];
    const float* W1      = (const float*)d_in[6];
    const float* b1      = (const float*)d_in[7];
    const float* W2      = (const float*)d_in[8];
    const float* b2      = (const float*)d_in[9];
    float* out = (float*)d_out;

    const int E = in_sizes[2];
    const int B = in_sizes[1] / E;
    const int D = in_sizes[7];              // 128
    const int N = in_sizes[0] / (B * D);

    zero_out_kernel<<<2048, 256>>>(out, (size_t)out_size);

    cudaFuncSetAttribute(cfconv_mma_kernel,
                         cudaFuncAttributeMaxDynamicSharedMemorySize, SMEM_TOTAL);
    cfconv_mma_kernel<<<296, THREADS, SMEM_TOTAL>>>(
        AF, dist, idx_j, seg_i, W1, b1, W2, b2, centers, gamma, out, B, N, E);
}

// round 16
// speedup vs baseline: 1.7881x; 1.0596x over previous
#include <cuda_runtime.h>
#include <cuda_fp16.h>
#include <cstdint>

#define THREADS 256
#define TILE_M  64
#define D_DIM   128
#define K_RBF   64

// strides in fp16 elements
#define W_STR   136      // 128 + 8 pad
#define A1_STR  72       // 64 + 8 pad
#define A2_STR  136
#define FB_STR  132      // halves per fbuf row (128 + 4 pad, 8B-mult for LDS.64)

// ---------------- smem layout (bytes) ----------------
#define OFF_W1H  0
#define OFF_W2H  (OFF_W1H + K_RBF * W_STR * 2)        // 17408
#define OFF_A1   (OFF_W2H + D_DIM * W_STR * 2)        // 52224
#define OFF_A2   (OFF_A1 + TILE_M * A1_STR * 2)       // 61440
#define OFF_FBUF OFF_A2                                // fp16 fbuf (16896 <= 17408)
#define OFF_B1S  (OFF_A2 + TILE_M * A2_STR * 2)       // 78848
#define OFF_B2S  (OFF_B1S + 512)
#define OFF_CEN  (OFF_B2S + 512)
#define OFF_GAM  (OFF_CEN + 256)
#define OFF_EMS  (OFF_GAM + 256)                       // int2[2][64]
#define SMEM_TOTAL (OFF_EMS + 1024)                    // 81408 -> 2 CTAs/SM

// ---------------- PTX helpers ----------------
static __device__ __forceinline__ uint32_t smem_u32(const void* p) {
    uint32_t a;
    asm("{ .reg .u64 t; cvta.to.shared.u64 t, %1; cvt.u32.u64 %0, t; }" : "=r"(a) : "l"(p));
    return a;
}

#define BAR_GRP(id) asm volatile("bar.sync %0, %1;" :: "r"(id), "r"(128) : "memory")

#define LDSM_X4(r, addr)                                                     \
    asm volatile("ldmatrix.sync.aligned.m8n8.x4.shared.b16 {%0,%1,%2,%3}, [%4];" \
        : "=r"((r)[0]), "=r"((r)[1]), "=r"((r)[2]), "=r"((r)[3]) : "r"(addr))

#define LDSM_X4T(r, addr)                                                    \
    asm volatile("ldmatrix.sync.aligned.m8n8.x4.trans.shared.b16 {%0,%1,%2,%3}, [%4];" \
        : "=r"((r)[0]), "=r"((r)[1]), "=r"((r)[2]), "=r"((r)[3]) : "r"(addr))

#define MMA_F16(c, a, b0, b1)                                                \
    asm("mma.sync.aligned.m16n8k16.row.col.f32.f16.f16.f32 "                \
        "{%0,%1,%2,%3}, {%4,%5,%6,%7}, {%8,%9}, {%0,%1,%2,%3};"             \
        : "+f"((c)[0]), "+f"((c)[1]), "+f"((c)[2]), "+f"((c)[3])            \
        : "r"((a)[0]), "r"((a)[1]), "r"((a)[2]), "r"((a)[3]),               \
          "r"(b0), "r"(b1))

// no-return vector reduction to global (sm_90+)
#define REDG_V4F32(addr, x, y, z, ww)                                        \
    asm volatile("red.global.add.v4.f32 [%0], {%1, %2, %3, %4};"            \
        :: "l"(addr), "f"(x), "f"(y), "f"(z), "f"(ww) : "memory")

static __device__ __forceinline__ float ssp(float x) {
    return fmaxf(x, 0.f) + __logf(1.f + __expf(-fabsf(x))) - 0.69314718055994531f;
}

static __device__ __forceinline__ uint32_t pack_f16x2(float f0, float f1) {
    uint32_t r;
    asm("cvt.rn.f16x2.f32 %0, %1, %2;" : "=r"(r) : "f"(f1), "f"(f0));
    return r;
}

__global__ void zero_out_kernel(float* __restrict__ out, size_t n) {
    size_t i = (size_t)blockIdx.x * blockDim.x + threadIdx.x;
    size_t stride = (size_t)gridDim.x * blockDim.x;
    for (; i < n; i += stride) out[i] = 0.f;
}

extern __shared__ char smem[];

__global__ void __launch_bounds__(THREADS, 2)
cfconv_mma_kernel(const float* __restrict__ AF,     // [B,N,D]
                  const float* __restrict__ dist,   // [B,E]
                  const int*   __restrict__ idx_j,  // [E]
                  const int*   __restrict__ seg_i,  // [E] sorted
                  const float* __restrict__ W1,     // [K,D]
                  const float* __restrict__ b1,
                  const float* __restrict__ W2,     // [D,D]
                  const float* __restrict__ b2,
                  const float* __restrict__ centers,
                  const float* __restrict__ gamma,
                  float* __restrict__ out,          // [B,N,D]
                  int B, int N, int E)
{
    const uint32_t sb = smem_u32(smem);
    const int tid  = threadIdx.x;
    const int w    = tid >> 5;
    const int lane = tid & 31;

    float*  b1s = (float*)(smem + OFF_B1S);
    float*  b2s = (float*)(smem + OFF_B2S);
    float*  cen = (float*)(smem + OFF_CEN);
    float*  gam = (float*)(smem + OFF_GAM);
    __half* fb  = (__half*)(smem + OFF_FBUF);

    // ---- weight prep: fp16, padded row-major [K][D] ----
    for (int i = tid; i < K_RBF * D_DIM; i += THREADS) {
        const int k = i >> 7, d = i & 127;
        *(__half*)(smem + OFF_W1H + (k * W_STR + d) * 2) = __float2half_rn(W1[i]);
    }
    for (int i = tid; i < D_DIM * D_DIM; i += THREADS) {
        const int k = i >> 7, d = i & 127;
        *(__half*)(smem + OFF_W2H + (k * W_STR + d) * 2) = __float2half_rn(W2[i]);
    }
    if (tid < D_DIM) { b1s[tid] = b1[tid]; b2s[tid] = b2[tid]; }
    else if (tid >= 128 && tid < 128 + K_RBF) {
        const int k = tid - 128; cen[k] = centers[k]; gam[k] = gamma[k];
    }
    __syncthreads();

    // warp tiling: 2x4 warp grid, each warp owns 32 edges x 32 cols
    const int wm = w & 1;              // row group (barrier id 1+wm, 128 threads)
    const int wn = w >> 1;             // col group 0..3
    const int r0 = wm * 32;
    const int d0 = wn * 32;
    const int arow = lane & 15;
    const int acol = (lane >> 4) * 8;
    const int gr   = lane >> 2;
    const int cc   = (lane & 3) * 2;

    const int tiles_pb = (E + TILE_M - 1) / TILE_M;
    const int total    = B * tiles_pb;

    // RBF phase: cen/gam vector-preloaded; writes A1 rows [r0,r0+32) + meta
    auto rbf_phase = [&](int gidx, int par) {
        const int bb_ = gidx / tiles_pb;
        const int e0_ = (gidx - bb_ * tiles_pb) * TILE_M;
        const int ne_ = min(TILE_M, E - e0_);
        const float* db_ = dist + (size_t)bb_ * E;
        const int el = r0 + lane;             // own group's edge row
        const int kb = wn * 16;
        const int eg = e0_ + min(el, ne_ - 1);
        const float dv = __ldg(&db_[eg]);
        float c4[16], g4[16];
        #pragma unroll
        for (int i = 0; i < 4; i++) {
            *(float4*)&c4[i * 4] = *(const float4*)&cen[kb + i * 4];
            *(float4*)&g4[i * 4] = *(const float4*)&gam[kb + i * 4];
        }
        #pragma unroll
        for (int kk = 0; kk < 16; kk += 2) {
            const float t0 = dv - c4[kk];
            const float t1 = dv - c4[kk + 1];
            const float v0 = __expf(-g4[kk]     * t0 * t0);
            const float v1 = __expf(-g4[kk + 1] * t1 * t1);
            const uint32_t byt = (uint32_t)(el * A1_STR + kb + kk) * 2;
            *(uint32_t*)(smem + OFF_A1 + byt) = pack_f16x2(v0, v1);
        }
        if (tid < TILE_M) {
            const int e = e0_ + min(tid, ne_ - 1);
            ((int2*)(smem + OFF_EMS))[par * TILE_M + tid] =
                make_int2(__ldg(&idx_j[e]), __ldg(&seg_i[e]));
        }
    };

    int parity = 0;
    const int g0 = blockIdx.x;
    if (g0 < total) rbf_phase(g0, parity);
    __syncthreads();

    for (int g = g0; g < total; g += gridDim.x) {
        const int b  = g / tiles_pb;
        const int e0 = (g - b * tiles_pb) * TILE_M;
        const int ne = min(TILE_M, E - e0);

        float c[2][4][4];
        #pragma unroll
        for (int mt = 0; mt < 2; mt++)
            #pragma unroll
            for (int nt = 0; nt < 4; nt++)
                { c[mt][nt][0]=0.f; c[mt][nt][1]=0.f; c[mt][nt][2]=0.f; c[mt][nt][3]=0.f; }

        // -------- GEMM1: [32x64] x W1[:,d0:d0+32] --------
        #pragma unroll
        for (int k = 0; k < 4; k++) {
            uint32_t a[2][4];
            #pragma unroll
            for (int mt = 0; mt < 2; mt++) {
                const uint32_t ab = (uint32_t)((r0 + mt*16 + arow) * A1_STR + k*16 + acol) * 2;
                LDSM_X4(a[mt], sb + OFF_A1 + ab);
            }
            const uint32_t brow = (uint32_t)((k*16 + arow) * W_STR + d0 + acol) * 2;
            #pragma unroll
            for (int p = 0; p < 2; p++) {
                uint32_t bh[4];
                LDSM_X4T(bh, sb + OFF_W1H + brow + (uint32_t)(p * 16) * 2);
                #pragma unroll
                for (int q = 0; q < 2; q++)
                    #pragma unroll
                    for (int mt = 0; mt < 2; mt++)
                        MMA_F16(c[mt][2*p+q], a[mt], bh[2*q], bh[2*q+1]);
            }
        }

        // -------- Epilogue 1: +b1 (float2), ssp, fp16 -> A2 --------
        #pragma unroll
        for (int mt = 0; mt < 2; mt++) {
            #pragma unroll
            for (int nt = 0; nt < 4; nt++) {
                const int col = d0 + nt*8 + cc;
                const float2 bb = *(const float2*)&b1s[col];
                const float f0 = ssp(c[mt][nt][0] + bb.x);
                const float f1 = ssp(c[mt][nt][1] + bb.y);
                const float f2 = ssp(c[mt][nt][2] + bb.x);
                const float f3 = ssp(c[mt][nt][3] + bb.y);
                const uint32_t r0b = (uint32_t)((r0 + mt*16 + gr)     * A2_STR + col) * 2;
                const uint32_t r1b = (uint32_t)((r0 + mt*16 + gr + 8) * A2_STR + col) * 2;
                *(uint32_t*)(smem + OFF_A2 + r0b) = pack_f16x2(f0, f1);
                *(uint32_t*)(smem + OFF_A2 + r1b) = pack_f16x2(f2, f3);
                c[mt][nt][0]=0.f; c[mt][nt][1]=0.f; c[mt][nt][2]=0.f; c[mt][nt][3]=0.f;
            }
        }
        BAR_GRP(1 + wm);   // A2 rows of this group complete

        // -------- GEMM2: [32x128] x W2[:,d0:d0+32] --------
        #pragma unroll
        for (int k = 0; k < 8; k++) {
            uint32_t a[2][4];
            #pragma unroll
            for (int mt = 0; mt < 2; mt++) {
                const uint32_t ab = (uint32_t)((r0 + mt*16 + arow) * A2_STR + k*16 + acol) * 2;
                LDSM_X4(a[mt], sb + OFF_A2 + ab);
            }
            const uint32_t brow = (uint32_t)((k*16 + arow) * W_STR + d0 + acol) * 2;
            #pragma unroll
            for (int p = 0; p < 2; p++) {
                uint32_t bh[4];
                LDSM_X4T(bh, sb + OFF_W2H + brow + (uint32_t)(p * 16) * 2);
                #pragma unroll
                for (int q = 0; q < 2; q++)
                    #pragma unroll
                    for (int mt = 0; mt < 2; mt++)
                        MMA_F16(c[mt][2*p+q], a[mt], bh[2*q], bh[2*q+1]);
            }
        }
        __syncthreads();   // ALL A2 reads done before fbuf (A2 overlay) writes

        // -------- Epilogue 2: +b2 (float2), ssp -> fbuf (fp16) --------
        #pragma unroll
        for (int mt = 0; mt < 2; mt++) {
            #pragma unroll
            for (int nt = 0; nt < 4; nt++) {
                const int col = d0 + nt*8 + cc;
                const float2 bb = *(const float2*)&b2s[col];
                const float f0 = ssp(c[mt][nt][0] + bb.x);
                const float f1 = ssp(c[mt][nt][1] + bb.y);
                const float f2 = ssp(c[mt][nt][2] + bb.x);
                const float f3 = ssp(c[mt][nt][3] + bb.y);
                *(uint32_t*)&fb[(r0 + mt*16 + gr)     * FB_STR + col] = pack_f16x2(f0, f1);
                *(uint32_t*)&fb[(r0 + mt*16 + gr + 8) * FB_STR + col] = pack_f16x2(f2, f3);
            }
        }
        __syncthreads();

        // -------- Overlap: RBF(next tile) -> A1  ||  gather(g) from fbuf --------
        const int gnext = g + gridDim.x;
        if (gnext < total) rbf_phase(gnext, parity ^ 1);

        {
            const int2* ems = (const int2*)(smem + OFF_EMS) + parity * TILE_M;
            const int ch = (tid & 31) * 4;      // channel quad (16B aligned)
            const int sp = tid >> 5;            // span 0..7 (8 edges each)
            const float* AFp = AF + (size_t)b * N * D_DIM;
            float*       Op  = out + (size_t)b * N * D_DIM;
            int cur = -1; float4 acc = make_float4(0.f, 0.f, 0.f, 0.f);
            const int e_beg = sp * 8;

            if (ne == TILE_M) {
                float4 m[8]; int sr[8];
                #pragma unroll
                for (int e = 0; e < 8; e++) {
                    const int2 js = ems[e_beg + e];
                    sr[e] = js.y;
                    const float4 af = *(const float4*)&AFp[(size_t)js.x * D_DIM + ch];
                    const __half2* fp = (const __half2*)&fb[(e_beg + e) * FB_STR + ch];
                    const float2 fl = __half22float2(fp[0]);
                    const float2 fh = __half22float2(fp[1]);
                    m[e] = make_float4(af.x * fl.x, af.y * fl.y, af.z * fh.x, af.w * fh.y);
                }
                #pragma unroll
                for (int e = 0; e < 8; e++) {
                    if (sr[e] != cur) {
                        if (cur >= 0) REDG_V4F32(&Op[(size_t)cur * D_DIM + ch],
                                                 acc.x, acc.y, acc.z, acc.w);
                        cur = sr[e]; acc = m[e];
                    } else {
                        acc.x += m[e].x; acc.y += m[e].y;
                        acc.z += m[e].z; acc.w += m[e].w;
                    }
                }
            } else {
                const int e_end = min(e_beg + 8, ne);
                for (int e = e_beg; e < e_end; e++) {
                    const int2 js = ems[e];
                    const float4 af = *(const float4*)&AFp[(size_t)js.x * D_DIM + ch];
                    const __half2* fp = (const __half2*)&fb[e * FB_STR + ch];
                    const float2 fl = __half22float2(fp[0]);
                    const float2 fh = __half22float2(fp[1]);
                    const float4 m = make_float4(af.x * fl.x, af.y * fl.y,
                                                 af.z * fh.x, af.w * fh.y);
                    if (js.y != cur) {
                        if (cur >= 0) REDG_V4F32(&Op[(size_t)cur * D_DIM + ch],
                                                 acc.x, acc.y, acc.z, acc.w);
                        cur = js.y; acc = m;
                    } else {
                        acc.x += m.x; acc.y += m.y; acc.z += m.z; acc.w += m.w;
                    }
                }
            }
            if (cur >= 0) REDG_V4F32(&Op[(size_t)cur * D_DIM + ch],
                                     acc.x, acc.y, acc.z, acc.w);
        }
        parity ^= 1;
        __syncthreads();   // gather done (fbuf free) & A1 ready for next GEMM1
    }
}

extern "C" void kernel_launch(void* const* d_in, const int* in_sizes, int n_in,
                              void* d_out, int out_size) {
    // order: atom_features, distances, idx_j, seg_i, centers, gamma, W1, b1, W2, b2
    const float* AF      = (const float*)d_in[0];
    const float* dist    = (const float*)d_in[1];
    const int*   idx_j   = (const int*)  d_in[2];
    const int*   seg_i   = (const int*)  d_in[3];
    const float* centers = (const float*)d_in[4];
    const float* gamma   = (const float*)d_in[5];
    const float* W1      = (const float*)d_in[6];
    const float* b1      = (const float*)d_in[7];
    const float* W2      = (const float*)d_in[8];
    const float* b2      = (const float*)d_in[9];
    float* out = (float*)d_out;

    const int E = in_sizes[2];
    const int B = in_sizes[1] / E;
    const int D = in_sizes[7];              // 128
    const int N = in_sizes[0] / (B * D);

    zero_out_kernel<<<2048, 256>>>(out, (size_t)out_size);

    cudaFuncSetAttribute(cfconv_mma_kernel,
                         cudaFuncAttributeMaxDynamicSharedMemorySize, SMEM_TOTAL);
    cfconv_mma_kernel<<<296, THREADS, SMEM_TOTAL>>>(
        AF, dist, idx_j, seg_i, W1, b1, W2, b2, centers, gamma, out, B, N, E);
}